// round 4
// baseline (speedup 1.0000x reference)
#include <cuda_runtime.h>
#include <cuda_bf16.h>
#include <math.h>

#define EE   400
#define HH   1150
#define VV   10000
#define TT   256
#define BB   32
#define M4H  4600
#define NROW 8192

typedef unsigned long long ull;

// ---- device scratch (static; no allocations allowed) ----
__device__ __align__(16) float g_P0[(size_t)NROW * M4H];   // emb@Wi0^T + b0
__device__ __align__(16) float g_h2all[(size_t)NROW * EE]; // layer2 h per step
__device__ __align__(16) float g_h0[2][HH * BB];           // [k][b], ping-pong
__device__ __align__(16) float g_h1[2][HH * BB];
__device__ __align__(16) float g_h2[2][EE * BB];
__device__ __align__(16) float g_c0s[HH * BB];
__device__ __align__(16) float g_c1s[HH * BB];
__device__ __align__(16) float g_c2s[EE * BB];

// ---- f32x2 helpers ----
__device__ __forceinline__ void fma2(ull& d, ull a, ull b) {
    asm("fma.rn.f32x2 %0, %1, %2, %0;" : "+l"(d) : "l"(a), "l"(b));
}
__device__ __forceinline__ ull dup2(float x) {
    ull r; asm("mov.b64 %0, {%1, %2};" : "=l"(r) : "f"(x), "f"(x)); return r;
}
__device__ __forceinline__ float2 unp2(ull v) {
    float2 r; asm("mov.b64 {%0, %1}, %2;" : "=f"(r.x), "=f"(r.y) : "l"(v)); return r;
}

// =======================================================================
// SGEMM: C[M,N] = A[M,400] * Bm[N,400]^T + bias.  64x64 tile, 256 threads.
// MODE 0: A rows gathered via gidx (embedding), C = g_P0.
// MODE 1: A = g_h2all, C = Cout (decoder output).
// =======================================================================
template<int MODE>
__global__ __launch_bounds__(256) void sgemm_nt(
    const float* __restrict__ A, const int* __restrict__ gidx,
    const float* __restrict__ Bm, const float* __restrict__ bias,
    float* __restrict__ Cout, int N)
{
    const int K = EE;
    __shared__ __align__(16) float As[16][68];
    __shared__ __align__(16) float Bs[16][68];

    float* C = (MODE == 0) ? g_P0 : Cout;
    const float* Abase = (MODE == 1) ? g_h2all : A;

    const int tid = threadIdx.x;
    const int bm = blockIdx.y * 64;
    const int bn = blockIdx.x * 64;

    const int r = tid >> 2, q = tid & 3;
    const float* arow = (MODE == 0)
        ? Abase + (size_t)gidx[bm + r] * K
        : Abase + (size_t)(bm + r) * K;
    const int nrow = bn + r;
    const bool bok = nrow < N;
    const float* brow = Bm + (size_t)(bok ? nrow : (N - 1)) * K;

    const int tx = tid & 15, ty = tid >> 4;

    ull acc[4][2];
#pragma unroll
    for (int i = 0; i < 4; ++i) { acc[i][0] = 0ull; acc[i][1] = 0ull; }

    for (int kc = 0; kc < K; kc += 16) {
        float4 av = *(const float4*)(arow + kc + q * 4);
        float4 bv = *(const float4*)(brow + kc + q * 4);
        if (!bok) { bv.x = 0.f; bv.y = 0.f; bv.z = 0.f; bv.w = 0.f; }
        __syncthreads();
        As[q*4+0][r] = av.x; As[q*4+1][r] = av.y; As[q*4+2][r] = av.z; As[q*4+3][r] = av.w;
        Bs[q*4+0][r] = bv.x; Bs[q*4+1][r] = bv.y; Bs[q*4+2][r] = bv.z; Bs[q*4+3][r] = bv.w;
        __syncthreads();
#pragma unroll
        for (int k = 0; k < 16; ++k) {
            ull b0 = *(const ull*)&Bs[k][tx*4];
            ull b1 = *(const ull*)&Bs[k][tx*4+2];
            float4 a4 = *(const float4*)&As[k][ty*4];
            ull a;
            a = dup2(a4.x); fma2(acc[0][0], a, b0); fma2(acc[0][1], a, b1);
            a = dup2(a4.y); fma2(acc[1][0], a, b0); fma2(acc[1][1], a, b1);
            a = dup2(a4.z); fma2(acc[2][0], a, b0); fma2(acc[2][1], a, b1);
            a = dup2(a4.w); fma2(acc[3][0], a, b0); fma2(acc[3][1], a, b1);
        }
    }

#pragma unroll
    for (int i = 0; i < 4; ++i) {
        int row = bm + ty * 4 + i;
        float2 c0 = unp2(acc[i][0]);
        float2 c1 = unp2(acc[i][1]);
        float v[4] = {c0.x, c0.y, c1.x, c1.y};
#pragma unroll
        for (int j = 0; j < 4; ++j) {
            int col = bn + tx * 4 + j;
            if (col < N) C[(size_t)row * N + col] = v[j] + bias[col];
        }
    }
}

// =======================================================================
// LSTM step. CTA: 8 j-cols x 4 gates (32 m-rows) x 32 batches, 128 threads.
// Double-buffered K-tiles of 32.  h layouts are [k][b] (b contiguous).
// =======================================================================
__device__ __forceinline__ void phase_accum(
    const float* __restrict__ W, const float* __restrict__ xsrc, int K,
    int j0, int OUT, int tid,
    float (*Ws)[32][32], float (*xs)[32][32], ull acc[2][2])
{
    const int ty = tid >> 3, tx = tid & 7;
    const int srow = tid >> 2, skk = (tid & 3) * 8;
    const int sgate = srow >> 3, sjj = srow & 7;
    const int sj = j0 + sjj;
    const bool wok = sj < OUT;
    const float* wrow = wok ? (W + (size_t)(sgate * OUT + sj) * K) : W;
    const int xk = tid >> 3;         // rows xk, xk+16
    const int xb = (tid & 7) * 4;

    const int ntiles = (K + 31) >> 5;
    float2 w[4]; float4 xv[2];

    // prologue: load tile 0 to regs, store buf 0
    {
#pragma unroll
        for (int i = 0; i < 4; ++i) {
            int kk = skk + i * 2;
            w[i] = (wok && kk + 1 < K) ? *(const float2*)(wrow + kk)
                                       : make_float2(0.f, 0.f);
        }
#pragma unroll
        for (int i = 0; i < 2; ++i) {
            int kr = xk + i * 16;
            xv[i] = (kr < K) ? *(const float4*)(xsrc + kr * 32 + xb)
                             : make_float4(0.f, 0.f, 0.f, 0.f);
        }
#pragma unroll
        for (int i = 0; i < 4; ++i) {
            Ws[0][skk + i*2    ][srow] = w[i].x;
            Ws[0][skk + i*2 + 1][srow] = w[i].y;
        }
#pragma unroll
        for (int i = 0; i < 2; ++i)
            *(float4*)&xs[0][xk + i*16][xb] = xv[i];
    }

    for (int tl = 0; tl < ntiles; ++tl) {
        __syncthreads();
        if (tl + 1 < ntiles) {
            int k0 = (tl + 1) << 5;
#pragma unroll
            for (int i = 0; i < 4; ++i) {
                int kk = skk + i * 2;
                w[i] = (wok && k0 + kk + 1 < K) ? *(const float2*)(wrow + k0 + kk)
                                                : make_float2(0.f, 0.f);
            }
#pragma unroll
            for (int i = 0; i < 2; ++i) {
                int kr = k0 + xk + i * 16;
                xv[i] = (kr < K) ? *(const float4*)(xsrc + kr * 32 + xb)
                                 : make_float4(0.f, 0.f, 0.f, 0.f);
            }
        }
        const int cb = tl & 1;
#pragma unroll
        for (int k = 0; k < 32; ++k) {
            float2 a  = *(const float2*)&Ws[cb][k][ty * 2];
            ull b0 = *(const ull*)&xs[cb][k][tx * 4];
            ull b1 = *(const ull*)&xs[cb][k][tx * 4 + 2];
            ull a0 = dup2(a.x), a1 = dup2(a.y);
            fma2(acc[0][0], a0, b0); fma2(acc[0][1], a0, b1);
            fma2(acc[1][0], a1, b0); fma2(acc[1][1], a1, b1);
        }
        if (tl + 1 < ntiles) {
            const int nb = (tl + 1) & 1;
#pragma unroll
            for (int i = 0; i < 4; ++i) {
                Ws[nb][skk + i*2    ][srow] = w[i].x;
                Ws[nb][skk + i*2 + 1][srow] = w[i].y;
            }
#pragma unroll
            for (int i = 0; i < 2; ++i)
                *(float4*)&xs[nb][xk + i*16][xb] = xv[i];
        }
    }
    __syncthreads();
}

template<int LAYER>
__global__ __launch_bounds__(128) void lstm_step_k(
    const float* __restrict__ Wx, const float* __restrict__ bx,
    const float* __restrict__ Wh, const float* __restrict__ bh,
    int t)
{
    constexpr int OUT = (LAYER == 2) ? EE : HH;
    constexpr int KX  = HH;
    constexpr int KH  = (LAYER == 2) ? EE : HH;

    __shared__ float Ws[2][32][32];
    __shared__ float xs[2][32][32];
    __shared__ float gbuf[32][32];

    const int tid = threadIdx.x;
    const int j0 = blockIdx.x * 8;
    const int par = t & 1;

    const float* xin  = (LAYER == 1) ? g_h0[par ^ 1]
                      : (LAYER == 2) ? g_h1[par ^ 1] : nullptr;
    const float* hold = (LAYER == 0) ? g_h0[par]
                      : (LAYER == 1) ? g_h1[par] : g_h2[par];
    float* hnew = (LAYER == 0) ? g_h0[par ^ 1]
                : (LAYER == 1) ? g_h1[par ^ 1] : g_h2[par ^ 1];
    float* cst  = (LAYER == 0) ? g_c0s : (LAYER == 1) ? g_c1s : g_c2s;

    ull acc[2][2] = {{0ull, 0ull}, {0ull, 0ull}};
    if (LAYER != 0) phase_accum(Wx, xin, KX, j0, OUT, tid, Ws, xs, acc);
    phase_accum(Wh, hold, KH, j0, OUT, tid, Ws, xs, acc);

    const int ty = tid >> 3, tx = tid & 7;
    *(ull*)&gbuf[ty*2    ][tx*4    ] = acc[0][0];
    *(ull*)&gbuf[ty*2    ][tx*4 + 2] = acc[0][1];
    *(ull*)&gbuf[ty*2 + 1][tx*4    ] = acc[1][0];
    *(ull*)&gbuf[ty*2 + 1][tx*4 + 2] = acc[1][1];
    __syncthreads();

#pragma unroll
    for (int it = 0; it < 2; ++it) {
        int item = tid + it * 128;
        int jj = item >> 5, b = item & 31;
        int j = j0 + jj;
        if (j < OUT) {
            float ip, fp, op, gp;
            if (LAYER == 0) {
                const float* p = g_P0 + (size_t)(t * 32 + b) * M4H + j;
                ip = gbuf[jj     ][b] + p[0]        + bh[j];
                fp = gbuf[8 + jj ][b] + p[HH]       + bh[HH + j];
                op = gbuf[16 + jj][b] + p[2 * HH]   + bh[2 * HH + j];
                gp = gbuf[24 + jj][b] + p[3 * HH]   + bh[3 * HH + j];
            } else {
                ip = gbuf[jj     ][b] + bx[j]           + bh[j];
                fp = gbuf[8 + jj ][b] + bx[OUT + j]     + bh[OUT + j];
                op = gbuf[16 + jj][b] + bx[2*OUT + j]   + bh[2*OUT + j];
                gp = gbuf[24 + jj][b] + bx[3*OUT + j]   + bh[3*OUT + j];
            }
            float gi = 1.f / (1.f + expf(-ip));
            float gf = 1.f / (1.f + expf(-fp));
            float go = 1.f / (1.f + expf(-op));
            float gg = tanhf(gp);
            float cn = gf * cst[j * 32 + b] + gi * gg;
            cst[j * 32 + b] = cn;
            float hv = go * tanhf(cn);
            hnew[j * 32 + b] = hv;
            if (LAYER == 2)
                g_h2all[(size_t)(t * 32 + b) * EE + j] = hv;
        }
    }
}

// ---- init: transpose harness states into [k][b] buffers ----
__global__ void init_states(const float* __restrict__ h0,
                            const float* __restrict__ c0,
                            const float* __restrict__ h0l,
                            const float* __restrict__ c0l)
{
    int idx = blockIdx.x * blockDim.x + threadIdx.x;
    if (idx < HH * BB) {
        int k = idx >> 5, b = idx & 31;
        g_h0[0][idx] = h0[b * HH + k];
        g_c0s[idx]   = c0[b * HH + k];
        g_h1[0][idx] = h0[BB * HH + b * HH + k];
        g_c1s[idx]   = c0[BB * HH + b * HH + k];
    }
    if (idx < EE * BB) {
        int k = idx >> 5, b = idx & 31;
        g_h2[0][idx] = h0l[b * EE + k];
        g_c2s[idx]   = c0l[b * EE + k];
    }
}

// ---- finalize: write state outputs after decoded block ----
__global__ void finalize_states(float* __restrict__ out)
{
    const size_t D1 = (size_t)TT * BB * VV;       // hf0 [2,B,H]
    const size_t D2 = D1 + 2 * BB * HH;           // hf1 [B,E]
    const size_t D3 = D2 + BB * EE;               // cf0 [2,B,H]
    const size_t D4 = D3 + 2 * BB * HH;           // cf1 [B,E]
    int idx = blockIdx.x * blockDim.x + threadIdx.x;
    if (idx < HH * BB) {
        int k = idx >> 5, b = idx & 31;
        out[D1 + b * HH + k]            = g_h0[0][idx];
        out[D1 + BB * HH + b * HH + k]  = g_h1[0][idx];
        out[D3 + b * HH + k]            = g_c0s[idx];
        out[D3 + BB * HH + b * HH + k]  = g_c1s[idx];
    }
    if (idx < EE * BB) {
        int k = idx >> 5, b = idx & 31;
        out[D2 + b * EE + k] = g_h2[0][idx];
        out[D4 + b * EE + k] = g_c2s[idx];
    }
}

// =======================================================================
extern "C" void kernel_launch(void* const* d_in, const int* in_sizes, int n_in,
                              void* d_out, int out_size)
{
    const int*   x    = (const int*)  d_in[0];
    const float* h0   = (const float*)d_in[1];
    const float* c0   = (const float*)d_in[2];
    const float* h0l  = (const float*)d_in[3];
    const float* c0l  = (const float*)d_in[4];
    const float* emb  = (const float*)d_in[5];
    const float* Wi0  = (const float*)d_in[6];
    const float* bi0  = (const float*)d_in[7];
    const float* Wh0  = (const float*)d_in[8];
    const float* bh0  = (const float*)d_in[9];
    const float* Wi1  = (const float*)d_in[10];
    const float* bi1  = (const float*)d_in[11];
    const float* Wh1  = (const float*)d_in[12];
    const float* bh1  = (const float*)d_in[13];
    const float* Wi2  = (const float*)d_in[14];
    const float* bi2  = (const float*)d_in[15];
    const float* Wh2  = (const float*)d_in[16];
    const float* bh2  = (const float*)d_in[17];
    const float* decW = (const float*)d_in[18];
    const float* decb = (const float*)d_in[19];
    float* out = (float*)d_out;

    // init states
    init_states<<<(HH * BB + 255) / 256, 256>>>(h0, c0, h0l, c0l);

    // P0 = emb[x] @ Wi0^T + bi0   (M=8192, N=4600, K=400)
    {
        dim3 g((M4H + 63) / 64, NROW / 64);
        sgemm_nt<0><<<g, 256>>>(emb, x, Wi0, bi0, nullptr, M4H);
    }

    // recurrence: 256 steps x 3 layers
    for (int t = 0; t < TT; ++t) {
        lstm_step_k<0><<<(HH + 7) / 8, 128>>>(nullptr, nullptr, Wh0, bh0, t);
        lstm_step_k<1><<<(HH + 7) / 8, 128>>>(Wi1, bi1, Wh1, bh1, t);
        lstm_step_k<2><<<(EE + 7) / 8, 128>>>(Wi2, bi2, Wh2, bh2, t);
    }

    // decoder: [8192,400] @ decW^T + decb  (N=10000)
    {
        dim3 g((VV + 63) / 64, NROW / 64);
        sgemm_nt<1><<<g, 256>>>(nullptr, nullptr, decW, decb, out, VV);
    }

    finalize_states<<<(HH * BB + 255) / 256, 256>>>(out);
}

// round 5
// speedup vs baseline: 1.4638x; 1.4638x over previous
#include <cuda_runtime.h>
#include <cuda_bf16.h>
#include <math.h>

#define EE   400
#define HH   1150
#define VV   10000
#define TT   256
#define BB   32
#define M4H  4600
#define NROW 8192

typedef unsigned long long ull;

// ---- device scratch (static; no allocations allowed) ----
__device__ __align__(16) float g_P0[(size_t)NROW * M4H];   // emb@Wi0^T + b0
__device__ __align__(16) float g_h2all[(size_t)NROW * EE]; // layer2 h per step
__device__ __align__(16) float g_h0[2][HH * BB];           // [k][b], ping-pong
__device__ __align__(16) float g_h1[2][HH * BB];
__device__ __align__(16) float g_h2[2][EE * BB];
__device__ __align__(16) float g_c0s[HH * BB];
__device__ __align__(16) float g_c1s[HH * BB];
__device__ __align__(16) float g_c2s[EE * BB];

// ---- f32x2 helpers ----
__device__ __forceinline__ void fma2(ull& d, ull a, ull b) {
    asm("fma.rn.f32x2 %0, %1, %2, %0;" : "+l"(d) : "l"(a), "l"(b));
}
__device__ __forceinline__ ull dup2(float x) {
    ull r; asm("mov.b64 %0, {%1, %2};" : "=l"(r) : "f"(x), "f"(x)); return r;
}
__device__ __forceinline__ float2 unp2(ull v) {
    float2 r; asm("mov.b64 {%0, %1}, %2;" : "=f"(r.x), "=f"(r.y) : "l"(v)); return r;
}
__device__ __forceinline__ void group_bar(int g) {
    asm volatile("bar.sync %0, 64;" :: "r"(g + 1) : "memory");
}

// =======================================================================
// SGEMM: C[M,N] = A[M,400] * Bm[N,400]^T + bias.  64x64 tile, 256 threads.
// MODE 0: A rows gathered via gidx (embedding), C = g_P0.
// MODE 1: A = g_h2all, C = Cout (decoder output).
// =======================================================================
template<int MODE>
__global__ __launch_bounds__(256) void sgemm_nt(
    const float* __restrict__ A, const int* __restrict__ gidx,
    const float* __restrict__ Bm, const float* __restrict__ bias,
    float* __restrict__ Cout, int N)
{
    const int K = EE;
    __shared__ __align__(16) float As[16][68];
    __shared__ __align__(16) float Bs[16][68];

    float* C = (MODE == 0) ? g_P0 : Cout;
    const float* Abase = (MODE == 1) ? g_h2all : A;

    const int tid = threadIdx.x;
    const int bm = blockIdx.y * 64;
    const int bn = blockIdx.x * 64;

    const int r = tid >> 2, q = tid & 3;
    const float* arow = (MODE == 0)
        ? Abase + (size_t)gidx[bm + r] * K
        : Abase + (size_t)(bm + r) * K;
    const int nrow = bn + r;
    const bool bok = nrow < N;
    const float* brow = Bm + (size_t)(bok ? nrow : (N - 1)) * K;

    const int tx = tid & 15, ty = tid >> 4;

    ull acc[4][2];
#pragma unroll
    for (int i = 0; i < 4; ++i) { acc[i][0] = 0ull; acc[i][1] = 0ull; }

    for (int kc = 0; kc < K; kc += 16) {
        float4 av = *(const float4*)(arow + kc + q * 4);
        float4 bv = *(const float4*)(brow + kc + q * 4);
        if (!bok) { bv.x = 0.f; bv.y = 0.f; bv.z = 0.f; bv.w = 0.f; }
        __syncthreads();
        As[q*4+0][r] = av.x; As[q*4+1][r] = av.y; As[q*4+2][r] = av.z; As[q*4+3][r] = av.w;
        Bs[q*4+0][r] = bv.x; Bs[q*4+1][r] = bv.y; Bs[q*4+2][r] = bv.z; Bs[q*4+3][r] = bv.w;
        __syncthreads();
#pragma unroll
        for (int k = 0; k < 16; ++k) {
            ull b0 = *(const ull*)&Bs[k][tx*4];
            ull b1 = *(const ull*)&Bs[k][tx*4+2];
            float4 a4 = *(const float4*)&As[k][ty*4];
            ull a;
            a = dup2(a4.x); fma2(acc[0][0], a, b0); fma2(acc[0][1], a, b1);
            a = dup2(a4.y); fma2(acc[1][0], a, b0); fma2(acc[1][1], a, b1);
            a = dup2(a4.z); fma2(acc[2][0], a, b0); fma2(acc[2][1], a, b1);
            a = dup2(a4.w); fma2(acc[3][0], a, b0); fma2(acc[3][1], a, b1);
        }
    }

#pragma unroll
    for (int i = 0; i < 4; ++i) {
        int row = bm + ty * 4 + i;
        float2 c0 = unp2(acc[i][0]);
        float2 c1 = unp2(acc[i][1]);
        float v[4] = {c0.x, c0.y, c1.x, c1.y};
#pragma unroll
        for (int j = 0; j < 4; ++j) {
            int col = bn + tx * 4 + j;
            if (col < N) C[(size_t)row * N + col] = v[j] + bias[col];
        }
    }
}

// =======================================================================
// LSTM step kernel, v2.
// CTA = 256 threads = 4 K-groups x 64 threads. Output tile 32 rows
// (4 gates x 8 j) x 32 batches. Each group handles K-tiles tl = g, g+4, ...
// of 32 k, double-buffered in its own SMEM region with group-local named
// barriers. Weights staged PRE-DUPLICATED as f32x2; inner loop per k is
// 3x LDS.128 + 8x FFMA2 (thread tile 4 rows x 4 batches).
// Partials reduced across groups via SMEM, then fused LSTM pointwise.
// =======================================================================
#define GRP_STRIDE 24576   // per-group: Wd 16KB (dup, 2 bufs) + xb 8KB (2 bufs)
#define WD_BYTES   16384
#define RED_OFF    98304   // 4*GRP_STRIDE
#define SMEM_STEP  114688  // RED_OFF + 16KB reduce buffer

template<int OUT>
__device__ __forceinline__ void phase_accum(
    const float* __restrict__ W, const float* __restrict__ xsrc, int K,
    int j0, int g, int gtid, ull* Wd, float* xb, ull acc[4][2])
{
    const int ntiles = (K + 31) >> 5;
    const int srow = gtid >> 1, shalf = gtid & 1;
    const int sgate = srow >> 3, sjj = srow & 7;
    const int sj = j0 + sjj;
    const bool wok = sj < OUT;
    const float* wrow = W + (size_t)(sgate * OUT + (wok ? sj : 0)) * K;
    const int ty = gtid >> 3, tx = gtid & 7;

    float wv[16];
    float4 xv[4];

    // ---- reg loads for one tile (W rows may be only 8B aligned: float2) ----
    auto load_regs = [&](int tl) {
        const int k0 = tl * 32;
#pragma unroll
        for (int c = 0; c < 8; ++c) {
            const int kk = k0 + shalf * 16 + c * 2;
            float2 v;
            if (wok && kk + 1 < K) {
                v = *(const float2*)(wrow + kk);
            } else {
                v.x = (wok && kk < K)     ? wrow[kk]     : 0.f;
                v.y = (wok && kk + 1 < K) ? wrow[kk + 1] : 0.f;
            }
            wv[c*2]   = v.x;
            wv[c*2+1] = v.y;
        }
#pragma unroll
        for (int c = 0; c < 4; ++c) {
            const int f = gtid + 64 * c;       // float4 index in 32x32 tile
            const int k = k0 + (f >> 3);
            xv[c] = (k < K) ? *(const float4*)(xsrc + (size_t)k * 32 + (f & 7) * 4)
                            : make_float4(0.f, 0.f, 0.f, 0.f);
        }
    };
    auto store_buf = [&](int buf) {
        ull*   wdst = Wd + buf * 1024;
        float* xdst = xb + buf * 1024;
#pragma unroll
        for (int c = 0; c < 16; ++c) {
            const int kk = shalf * 16 + c;
            wdst[kk * 32 + srow] = dup2(wv[c]);
        }
#pragma unroll
        for (int c = 0; c < 4; ++c) {
            const int f = gtid + 64 * c;
            *(float4*)(xdst + f * 4) = xv[c];
        }
    };

    load_regs(g);
    store_buf(0);
    group_bar(g);

    int cur = 0;
    for (int tl = g; tl < ntiles; tl += 4) {
        const bool more = (tl + 4) < ntiles;
        if (more) load_regs(tl + 4);

        const ull*   bw  = Wd + cur * 1024;
        const float* bxs = xb + cur * 1024;
#pragma unroll
        for (int k = 0; k < 32; ++k) {
            ulonglong2 a01 = *(const ulonglong2*)(bw + k * 32 + ty * 4);
            ulonglong2 a23 = *(const ulonglong2*)(bw + k * 32 + ty * 4 + 2);
            ulonglong2 bv  = *(const ulonglong2*)(bxs + k * 32 + tx * 4);
            fma2(acc[0][0], a01.x, bv.x); fma2(acc[0][1], a01.x, bv.y);
            fma2(acc[1][0], a01.y, bv.x); fma2(acc[1][1], a01.y, bv.y);
            fma2(acc[2][0], a23.x, bv.x); fma2(acc[2][1], a23.x, bv.y);
            fma2(acc[3][0], a23.y, bv.x); fma2(acc[3][1], a23.y, bv.y);
        }
        if (more) store_buf(cur ^ 1);
        group_bar(g);
        cur ^= 1;
    }
}

template<int LAYER>
__global__ __launch_bounds__(256) void lstm_step_k(
    const float* __restrict__ Wx, const float* __restrict__ bx,
    const float* __restrict__ Wh, const float* __restrict__ bh,
    int t)
{
    constexpr int OUT = (LAYER == 2) ? EE : HH;
    constexpr int KH  = (LAYER == 2) ? EE : HH;

    extern __shared__ __align__(16) char smem[];
    const int tid = threadIdx.x;
    const int g = tid >> 6, gtid = tid & 63;
    const int ty = gtid >> 3, tx = gtid & 7;

    ull*   Wd  = (ull*)  (smem + g * GRP_STRIDE);
    float* xb  = (float*)(smem + g * GRP_STRIDE + WD_BYTES);
    float* red = (float*)(smem + RED_OFF);

    const int j0 = blockIdx.x * 8;
    const int par = t & 1;

    const float* xin  = (LAYER == 1) ? g_h0[par ^ 1]
                      : (LAYER == 2) ? g_h1[par ^ 1] : nullptr;
    const float* hold = (LAYER == 0) ? g_h0[par]
                      : (LAYER == 1) ? g_h1[par] : g_h2[par];
    float* hnew = (LAYER == 0) ? g_h0[par ^ 1]
                : (LAYER == 1) ? g_h1[par ^ 1] : g_h2[par ^ 1];
    float* cst  = (LAYER == 0) ? g_c0s : (LAYER == 1) ? g_c1s : g_c2s;

    ull acc[4][2] = {{0ull, 0ull}, {0ull, 0ull}, {0ull, 0ull}, {0ull, 0ull}};
    if (LAYER != 0) phase_accum<OUT>(Wx, xin, HH, j0, g, gtid, Wd, xb, acc);
    phase_accum<OUT>(Wh, hold, KH, j0, g, gtid, Wd, xb, acc);

    // ---- stage partials, reduce across the 4 K-groups ----
    float* redp = red + g * 1024;
#pragma unroll
    for (int r = 0; r < 4; ++r) {
        *(ull*)(redp + (ty * 4 + r) * 32 + tx * 4)     = acc[r][0];
        *(ull*)(redp + (ty * 4 + r) * 32 + tx * 4 + 2) = acc[r][1];
    }
    __syncthreads();

    // ---- fused LSTM pointwise: 256 threads = 8 j x 32 b ----
    const int jj = tid >> 5, b = tid & 31;
    const int j = j0 + jj;
    if (j < OUT) {
        float pre[4];
#pragma unroll
        for (int gate = 0; gate < 4; ++gate) {
            const int row = gate * 8 + jj;
            pre[gate] = red[row * 32 + b] + red[1024 + row * 32 + b]
                      + red[2048 + row * 32 + b] + red[3072 + row * 32 + b];
        }
        float ip, fp, op, gp;
        if (LAYER == 0) {
            const float* p = g_P0 + (size_t)(t * 32 + b) * M4H + j;
            ip = pre[0] + p[0]      + bh[j];
            fp = pre[1] + p[HH]     + bh[HH + j];
            op = pre[2] + p[2 * HH] + bh[2 * HH + j];
            gp = pre[3] + p[3 * HH] + bh[3 * HH + j];
        } else {
            ip = pre[0] + bx[j]           + bh[j];
            fp = pre[1] + bx[OUT + j]     + bh[OUT + j];
            op = pre[2] + bx[2 * OUT + j] + bh[2 * OUT + j];
            gp = pre[3] + bx[3 * OUT + j] + bh[3 * OUT + j];
        }
        const float gi = 1.f / (1.f + expf(-ip));
        const float gf = 1.f / (1.f + expf(-fp));
        const float go = 1.f / (1.f + expf(-op));
        const float gg = tanhf(gp);
        const float cn = gf * cst[j * 32 + b] + gi * gg;
        cst[j * 32 + b] = cn;
        const float hv = go * tanhf(cn);
        hnew[j * 32 + b] = hv;
        if (LAYER == 2)
            g_h2all[(size_t)(t * 32 + b) * EE + j] = hv;
    }
}

// ---- init: transpose harness states into [k][b] buffers ----
__global__ void init_states(const float* __restrict__ h0,
                            const float* __restrict__ c0,
                            const float* __restrict__ h0l,
                            const float* __restrict__ c0l)
{
    int idx = blockIdx.x * blockDim.x + threadIdx.x;
    if (idx < HH * BB) {
        int k = idx >> 5, b = idx & 31;
        g_h0[0][idx] = h0[b * HH + k];
        g_c0s[idx]   = c0[b * HH + k];
        g_h1[0][idx] = h0[BB * HH + b * HH + k];
        g_c1s[idx]   = c0[BB * HH + b * HH + k];
    }
    if (idx < EE * BB) {
        int k = idx >> 5, b = idx & 31;
        g_h2[0][idx] = h0l[b * EE + k];
        g_c2s[idx]   = c0l[b * EE + k];
    }
}

// ---- finalize: write state outputs after decoded block ----
__global__ void finalize_states(float* __restrict__ out)
{
    const size_t D1 = (size_t)TT * BB * VV;       // hf0 [2,B,H]
    const size_t D2 = D1 + 2 * BB * HH;           // hf1 [B,E]
    const size_t D3 = D2 + BB * EE;               // cf0 [2,B,H]
    const size_t D4 = D3 + 2 * BB * HH;           // cf1 [B,E]
    int idx = blockIdx.x * blockDim.x + threadIdx.x;
    if (idx < HH * BB) {
        int k = idx >> 5, b = idx & 31;
        out[D1 + b * HH + k]            = g_h0[0][idx];
        out[D1 + BB * HH + b * HH + k]  = g_h1[0][idx];
        out[D3 + b * HH + k]            = g_c0s[idx];
        out[D3 + BB * HH + b * HH + k]  = g_c1s[idx];
    }
    if (idx < EE * BB) {
        int k = idx >> 5, b = idx & 31;
        out[D2 + b * EE + k] = g_h2[0][idx];
        out[D4 + b * EE + k] = g_c2s[idx];
    }
}

// =======================================================================
extern "C" void kernel_launch(void* const* d_in, const int* in_sizes, int n_in,
                              void* d_out, int out_size)
{
    const int*   x    = (const int*)  d_in[0];
    const float* h0   = (const float*)d_in[1];
    const float* c0   = (const float*)d_in[2];
    const float* h0l  = (const float*)d_in[3];
    const float* c0l  = (const float*)d_in[4];
    const float* emb  = (const float*)d_in[5];
    const float* Wi0  = (const float*)d_in[6];
    const float* bi0  = (const float*)d_in[7];
    const float* Wh0  = (const float*)d_in[8];
    const float* bh0  = (const float*)d_in[9];
    const float* Wi1  = (const float*)d_in[10];
    const float* bi1  = (const float*)d_in[11];
    const float* Wh1  = (const float*)d_in[12];
    const float* bh1  = (const float*)d_in[13];
    const float* Wi2  = (const float*)d_in[14];
    const float* bi2  = (const float*)d_in[15];
    const float* Wh2  = (const float*)d_in[16];
    const float* bh2  = (const float*)d_in[17];
    const float* decW = (const float*)d_in[18];
    const float* decb = (const float*)d_in[19];
    float* out = (float*)d_out;

    // opt-in to 112KB dynamic smem (idempotent; host-side, not captured)
    cudaFuncSetAttribute(lstm_step_k<0>, cudaFuncAttributeMaxDynamicSharedMemorySize, SMEM_STEP);
    cudaFuncSetAttribute(lstm_step_k<1>, cudaFuncAttributeMaxDynamicSharedMemorySize, SMEM_STEP);
    cudaFuncSetAttribute(lstm_step_k<2>, cudaFuncAttributeMaxDynamicSharedMemorySize, SMEM_STEP);

    // init states
    init_states<<<(HH * BB + 255) / 256, 256>>>(h0, c0, h0l, c0l);

    // P0 = emb[x] @ Wi0^T + bi0   (M=8192, N=4600, K=400)
    {
        dim3 g((M4H + 63) / 64, NROW / 64);
        sgemm_nt<0><<<g, 256>>>(emb, x, Wi0, bi0, nullptr, M4H);
    }

    // recurrence: 256 steps x 3 layers
    for (int t = 0; t < TT; ++t) {
        lstm_step_k<0><<<(HH + 7) / 8, 256, SMEM_STEP>>>(nullptr, nullptr, Wh0, bh0, t);
        lstm_step_k<1><<<(HH + 7) / 8, 256, SMEM_STEP>>>(Wi1, bi1, Wh1, bh1, t);
        lstm_step_k<2><<<(EE + 7) / 8, 256, SMEM_STEP>>>(Wi2, bi2, Wh2, bh2, t);
    }

    // decoder: [8192,400] @ decW^T + decb  (N=10000)
    {
        dim3 g((VV + 63) / 64, NROW / 64);
        sgemm_nt<1><<<g, 256>>>(nullptr, nullptr, decW, decb, out, VV);
    }

    finalize_states<<<(HH * BB + 255) / 256, 256>>>(out);
}

// round 6
// speedup vs baseline: 1.7126x; 1.1700x over previous
#include <cuda_runtime.h>
#include <cuda_bf16.h>
#include <math.h>

#define EE   400
#define HH   1150
#define VV   10000
#define TT   256
#define BB   32
#define M4H  4600
#define NROW 8192

typedef unsigned long long ull;

// ---- device scratch (static; no allocations allowed) ----
__device__ __align__(16) float g_P0[(size_t)NROW * M4H];   // emb@Wi0^T + b0
__device__ __align__(16) float g_h2all[(size_t)NROW * EE]; // layer2 h per step
__device__ __align__(16) float g_h0[2][HH * BB];           // [k][b], ping-pong
__device__ __align__(16) float g_h1[2][HH * BB];
__device__ __align__(16) float g_h2[2][EE * BB];
__device__ __align__(16) float g_c0s[HH * BB];
__device__ __align__(16) float g_c1s[HH * BB];
__device__ __align__(16) float g_c2s[EE * BB];

// ---- f32x2 helpers ----
__device__ __forceinline__ void fma2(ull& d, ull a, ull b) {
    asm("fma.rn.f32x2 %0, %1, %2, %0;" : "+l"(d) : "l"(a), "l"(b));
}
__device__ __forceinline__ ull dup2(float x) {
    ull r; asm("mov.b64 %0, {%1, %2};" : "=l"(r) : "f"(x), "f"(x)); return r;
}
__device__ __forceinline__ float2 unp2(ull v) {
    float2 r; asm("mov.b64 {%0, %1}, %2;" : "=f"(r.x), "=f"(r.y) : "l"(v)); return r;
}

// =======================================================================
// SGEMM: C[M,N] = A[M,400] * Bm[N,400]^T + bias.  64x64 tile, 256 threads.
// MODE 0: A rows gathered via gidx (embedding), C = g_P0.
// MODE 1: A = g_h2all, C = Cout (decoder output).
// =======================================================================
template<int MODE>
__global__ __launch_bounds__(256) void sgemm_nt(
    const float* __restrict__ A, const int* __restrict__ gidx,
    const float* __restrict__ Bm, const float* __restrict__ bias,
    float* __restrict__ Cout, int N)
{
    const int K = EE;
    __shared__ __align__(16) float As[16][68];
    __shared__ __align__(16) float Bs[16][68];

    float* C = (MODE == 0) ? g_P0 : Cout;
    const float* Abase = (MODE == 1) ? g_h2all : A;

    const int tid = threadIdx.x;
    const int bm = blockIdx.y * 64;
    const int bn = blockIdx.x * 64;

    const int r = tid >> 2, q = tid & 3;
    const float* arow = (MODE == 0)
        ? Abase + (size_t)gidx[bm + r] * K
        : Abase + (size_t)(bm + r) * K;
    const int nrow = bn + r;
    const bool bok = nrow < N;
    const float* brow = Bm + (size_t)(bok ? nrow : (N - 1)) * K;

    const int tx = tid & 15, ty = tid >> 4;

    ull acc[4][2];
#pragma unroll
    for (int i = 0; i < 4; ++i) { acc[i][0] = 0ull; acc[i][1] = 0ull; }

    for (int kc = 0; kc < K; kc += 16) {
        float4 av = *(const float4*)(arow + kc + q * 4);
        float4 bv = *(const float4*)(brow + kc + q * 4);
        if (!bok) { bv.x = 0.f; bv.y = 0.f; bv.z = 0.f; bv.w = 0.f; }
        __syncthreads();
        As[q*4+0][r] = av.x; As[q*4+1][r] = av.y; As[q*4+2][r] = av.z; As[q*4+3][r] = av.w;
        Bs[q*4+0][r] = bv.x; Bs[q*4+1][r] = bv.y; Bs[q*4+2][r] = bv.z; Bs[q*4+3][r] = bv.w;
        __syncthreads();
#pragma unroll
        for (int k = 0; k < 16; ++k) {
            ull b0 = *(const ull*)&Bs[k][tx*4];
            ull b1 = *(const ull*)&Bs[k][tx*4+2];
            float4 a4 = *(const float4*)&As[k][ty*4];
            ull a;
            a = dup2(a4.x); fma2(acc[0][0], a, b0); fma2(acc[0][1], a, b1);
            a = dup2(a4.y); fma2(acc[1][0], a, b0); fma2(acc[1][1], a, b1);
            a = dup2(a4.z); fma2(acc[2][0], a, b0); fma2(acc[2][1], a, b1);
            a = dup2(a4.w); fma2(acc[3][0], a, b0); fma2(acc[3][1], a, b1);
        }
    }

#pragma unroll
    for (int i = 0; i < 4; ++i) {
        int row = bm + ty * 4 + i;
        float2 c0 = unp2(acc[i][0]);
        float2 c1 = unp2(acc[i][1]);
        float v[4] = {c0.x, c0.y, c1.x, c1.y};
#pragma unroll
        for (int j = 0; j < 4; ++j) {
            int col = bn + tx * 4 + j;
            if (col < N) C[(size_t)row * N + col] = v[j] + bias[col];
        }
    }
}

// =======================================================================
// LSTM step kernel v3: warp-private K-slices, no cross-warp barriers.
// CTA = 8 warps. Output tile: 32 rows (4 gates x 8 j) x 32 batches.
// Warp w processes k-tiles (KT=16) tl = w, w+8, ..., double-buffered in its
// private smem slice (Wd pre-duplicated ull + xs floats). Lane =
// (rg 0..7, bg 0..3); thread tile 4 rows x 4 batch-pairs (16 f32x2 accs).
// All LDS are broadcast-friendly (1 phase each). 8 partial tiles reduced
// via smem, then fused LSTM pointwise.
// =======================================================================
#define KT        16
#define WSLICE    12288                 // per-warp: Wd 2*4KB + xs 2*2KB
#define RED_OFF   (8 * WSLICE)          // 98304
#define SMEM_STEP (RED_OFF + 32768)     // 131072

struct WarpCtx {
    ull*   Wd;     // [2][KT][32] ull
    float* xs;     // [2][KT][32] float
    int lane, rg, bg;
    bool wok;      // this lane's W row valid
    int rowlocal;  // 0..31 (gate*8+jj)
};

template<int OUT>
__device__ __forceinline__ void phase_accum(
    const float* __restrict__ W, const float* __restrict__ xsrc, int K,
    int j0, int w, const WarpCtx& C, ull acc[4][4])
{
    const int ntiles = (K + KT - 1) / KT;
    const int gate = C.rowlocal >> 3, jj = C.rowlocal & 7;
    const float* wrow = W + (size_t)(gate * OUT + (C.wok ? (j0 + jj) : 0)) * K;

    float2 wv[8];
    float4 xv[4];

    auto load_regs = [&](int tl) {
        const int k0 = tl * KT;
#pragma unroll
        for (int c = 0; c < 8; ++c) {
            const int kk = k0 + c * 2;
            float2 v;
            if (C.wok && kk + 1 < K) v = *(const float2*)(wrow + kk);
            else {
                v.x = (C.wok && kk < K) ? wrow[kk] : 0.f;
                v.y = 0.f;
            }
            wv[c] = v;
        }
#pragma unroll
        for (int c = 0; c < 4; ++c) {
            const int f = C.lane + 32 * c;
            const int k = k0 + (f >> 3);
            xv[c] = (k < K) ? *(const float4*)(xsrc + (size_t)k * 32 + (f & 7) * 4)
                            : make_float4(0.f, 0.f, 0.f, 0.f);
        }
    };
    auto store_buf = [&](int buf) {
        ull*   wd = C.Wd + buf * (KT * 32);
        float* xd = C.xs + buf * (KT * 32);
#pragma unroll
        for (int c = 0; c < 8; ++c) {
            wd[(c * 2    ) * 32 + C.lane] = dup2(wv[c].x);
            wd[(c * 2 + 1) * 32 + C.lane] = dup2(wv[c].y);
        }
#pragma unroll
        for (int c = 0; c < 4; ++c) {
            const int f = C.lane + 32 * c;
            *(float4*)(xd + (f >> 3) * 32 + (f & 7) * 4) = xv[c];
        }
    };

    load_regs(w);
    store_buf(0);
    __syncwarp();

    int cur = 0;
    for (int tl = w; tl < ntiles; tl += 8) {
        const bool more = (tl + 8) < ntiles;
        if (more) load_regs(tl + 8);

        const ull*   bw = C.Wd + cur * (KT * 32);
        const float* bx = C.xs + cur * (KT * 32);
#pragma unroll
        for (int k = 0; k < KT; ++k) {
            ulonglong2 w01 = *(const ulonglong2*)(bw + k * 32 + C.rg * 4);
            ulonglong2 w23 = *(const ulonglong2*)(bw + k * 32 + C.rg * 4 + 2);
            ulonglong2 x01 = *(const ulonglong2*)(bx + k * 32 + C.bg * 8);
            ulonglong2 x23 = *(const ulonglong2*)(bx + k * 32 + C.bg * 8 + 4);
            fma2(acc[0][0], w01.x, x01.x); fma2(acc[0][1], w01.x, x01.y);
            fma2(acc[0][2], w01.x, x23.x); fma2(acc[0][3], w01.x, x23.y);
            fma2(acc[1][0], w01.y, x01.x); fma2(acc[1][1], w01.y, x01.y);
            fma2(acc[1][2], w01.y, x23.x); fma2(acc[1][3], w01.y, x23.y);
            fma2(acc[2][0], w23.x, x01.x); fma2(acc[2][1], w23.x, x01.y);
            fma2(acc[2][2], w23.x, x23.x); fma2(acc[2][3], w23.x, x23.y);
            fma2(acc[3][0], w23.y, x01.x); fma2(acc[3][1], w23.y, x01.y);
            fma2(acc[3][2], w23.y, x23.x); fma2(acc[3][3], w23.y, x23.y);
        }
        if (more) store_buf(cur ^ 1);
        __syncwarp();
        cur ^= 1;
    }
}

template<int LAYER>
__global__ __launch_bounds__(256) void lstm_step_k(
    const float* __restrict__ Wx, const float* __restrict__ bx,
    const float* __restrict__ Wh, const float* __restrict__ bh,
    int t)
{
    constexpr int OUT = (LAYER == 2) ? EE : HH;
    constexpr int KH  = (LAYER == 2) ? EE : HH;

    extern __shared__ __align__(16) char smem[];
    const int tid  = threadIdx.x;
    const int w    = tid >> 5;
    const int lane = tid & 31;
    const int j0   = blockIdx.x * 8;
    const int par  = t & 1;

    WarpCtx C;
    C.Wd = (ull*)(smem + w * WSLICE);
    C.xs = (float*)(smem + w * WSLICE + 8192);
    C.lane = lane;
    C.rg = lane >> 2;
    C.bg = lane & 3;
    C.rowlocal = lane;
    C.wok = (j0 + (lane & 7)) < OUT;
    float* red = (float*)(smem + RED_OFF);   // [8][32][32]

    const float* xin  = (LAYER == 1) ? g_h0[par ^ 1]
                      : (LAYER == 2) ? g_h1[par ^ 1] : nullptr;
    const float* hold = (LAYER == 0) ? g_h0[par]
                      : (LAYER == 1) ? g_h1[par] : g_h2[par];
    float* hnew = (LAYER == 0) ? g_h0[par ^ 1]
                : (LAYER == 1) ? g_h1[par ^ 1] : g_h2[par ^ 1];
    float* cst  = (LAYER == 0) ? g_c0s : (LAYER == 1) ? g_c1s : g_c2s;

    ull acc[4][4];
#pragma unroll
    for (int r = 0; r < 4; ++r)
#pragma unroll
        for (int i = 0; i < 4; ++i) acc[r][i] = 0ull;

    if (LAYER != 0) phase_accum<OUT>(Wx, xin, HH, j0, w, C, acc);
    phase_accum<OUT>(Wh, hold, KH, j0, w, C, acc);

    // ---- stage 8 partial tiles ----
    float* redw = red + w * 1024;
#pragma unroll
    for (int r = 0; r < 4; ++r) {
        const int row = C.rg * 4 + r;
        ulonglong2 p0; p0.x = acc[r][0]; p0.y = acc[r][1];
        ulonglong2 p1; p1.x = acc[r][2]; p1.y = acc[r][3];
        *(ulonglong2*)(redw + row * 32 + C.bg * 8)     = p0;
        *(ulonglong2*)(redw + row * 32 + C.bg * 8 + 4) = p1;
    }
    __syncthreads();

    // ---- reduce + fused LSTM pointwise: thread = (jj, b) ----
    const int jj = tid >> 5, b = tid & 31;
    const int j = j0 + jj;
    if (j < OUT) {
        float pre[4];
#pragma unroll
        for (int gate = 0; gate < 4; ++gate) {
            const int row = gate * 8 + jj;
            float s = 0.f;
#pragma unroll
            for (int ww = 0; ww < 8; ++ww)
                s += red[ww * 1024 + row * 32 + b];
            pre[gate] = s;
        }
        float ip, fp, op, gp;
        if (LAYER == 0) {
            const float* p = g_P0 + (size_t)(t * 32 + b) * M4H + j;
            ip = pre[0] + p[0]      + bh[j];
            fp = pre[1] + p[HH]     + bh[HH + j];
            op = pre[2] + p[2 * HH] + bh[2 * HH + j];
            gp = pre[3] + p[3 * HH] + bh[3 * HH + j];
        } else {
            ip = pre[0] + bx[j]           + bh[j];
            fp = pre[1] + bx[OUT + j]     + bh[OUT + j];
            op = pre[2] + bx[2 * OUT + j] + bh[2 * OUT + j];
            gp = pre[3] + bx[3 * OUT + j] + bh[3 * OUT + j];
        }
        const float gi = 1.f / (1.f + expf(-ip));
        const float gf = 1.f / (1.f + expf(-fp));
        const float go = 1.f / (1.f + expf(-op));
        const float gg = tanhf(gp);
        const float cn = gf * cst[j * 32 + b] + gi * gg;
        cst[j * 32 + b] = cn;
        const float hv = go * tanhf(cn);
        hnew[j * 32 + b] = hv;
        if (LAYER == 2)
            g_h2all[(size_t)(t * 32 + b) * EE + j] = hv;
    }
}

// ---- init: transpose harness states into [k][b] buffers ----
__global__ void init_states(const float* __restrict__ h0,
                            const float* __restrict__ c0,
                            const float* __restrict__ h0l,
                            const float* __restrict__ c0l)
{
    int idx = blockIdx.x * blockDim.x + threadIdx.x;
    if (idx < HH * BB) {
        int k = idx >> 5, b = idx & 31;
        g_h0[0][idx] = h0[b * HH + k];
        g_c0s[idx]   = c0[b * HH + k];
        g_h1[0][idx] = h0[BB * HH + b * HH + k];
        g_c1s[idx]   = c0[BB * HH + b * HH + k];
    }
    if (idx < EE * BB) {
        int k = idx >> 5, b = idx & 31;
        g_h2[0][idx] = h0l[b * EE + k];
        g_c2s[idx]   = c0l[b * EE + k];
    }
}

// ---- finalize: write state outputs after decoded block ----
__global__ void finalize_states(float* __restrict__ out)
{
    const size_t D1 = (size_t)TT * BB * VV;       // hf0 [2,B,H]
    const size_t D2 = D1 + 2 * BB * HH;           // hf1 [B,E]
    const size_t D3 = D2 + BB * EE;               // cf0 [2,B,H]
    const size_t D4 = D3 + 2 * BB * HH;           // cf1 [B,E]
    int idx = blockIdx.x * blockDim.x + threadIdx.x;
    if (idx < HH * BB) {
        int k = idx >> 5, b = idx & 31;
        out[D1 + b * HH + k]            = g_h0[0][idx];
        out[D1 + BB * HH + b * HH + k]  = g_h1[0][idx];
        out[D3 + b * HH + k]            = g_c0s[idx];
        out[D3 + BB * HH + b * HH + k]  = g_c1s[idx];
    }
    if (idx < EE * BB) {
        int k = idx >> 5, b = idx & 31;
        out[D2 + b * EE + k] = g_h2[0][idx];
        out[D4 + b * EE + k] = g_c2s[idx];
    }
}

// =======================================================================
extern "C" void kernel_launch(void* const* d_in, const int* in_sizes, int n_in,
                              void* d_out, int out_size)
{
    const int*   x    = (const int*)  d_in[0];
    const float* h0   = (const float*)d_in[1];
    const float* c0   = (const float*)d_in[2];
    const float* h0l  = (const float*)d_in[3];
    const float* c0l  = (const float*)d_in[4];
    const float* emb  = (const float*)d_in[5];
    const float* Wi0  = (const float*)d_in[6];
    const float* bi0  = (const float*)d_in[7];
    const float* Wh0  = (const float*)d_in[8];
    const float* bh0  = (const float*)d_in[9];
    const float* Wi1  = (const float*)d_in[10];
    const float* bi1  = (const float*)d_in[11];
    const float* Wh1  = (const float*)d_in[12];
    const float* bh1  = (const float*)d_in[13];
    const float* Wi2  = (const float*)d_in[14];
    const float* bi2  = (const float*)d_in[15];
    const float* Wh2  = (const float*)d_in[16];
    const float* bh2  = (const float*)d_in[17];
    const float* decW = (const float*)d_in[18];
    const float* decb = (const float*)d_in[19];
    float* out = (float*)d_out;

    cudaFuncSetAttribute(lstm_step_k<0>, cudaFuncAttributeMaxDynamicSharedMemorySize, SMEM_STEP);
    cudaFuncSetAttribute(lstm_step_k<1>, cudaFuncAttributeMaxDynamicSharedMemorySize, SMEM_STEP);
    cudaFuncSetAttribute(lstm_step_k<2>, cudaFuncAttributeMaxDynamicSharedMemorySize, SMEM_STEP);

    init_states<<<(HH * BB + 255) / 256, 256>>>(h0, c0, h0l, c0l);

    // P0 = emb[x] @ Wi0^T + bi0   (M=8192, N=4600, K=400)
    {
        dim3 g((M4H + 63) / 64, NROW / 64);
        sgemm_nt<0><<<g, 256>>>(emb, x, Wi0, bi0, nullptr, M4H);
    }

    // recurrence: 256 steps x 3 layers
    for (int t = 0; t < TT; ++t) {
        lstm_step_k<0><<<(HH + 7) / 8, 256, SMEM_STEP>>>(nullptr, nullptr, Wh0, bh0, t);
        lstm_step_k<1><<<(HH + 7) / 8, 256, SMEM_STEP>>>(Wi1, bi1, Wh1, bh1, t);
        lstm_step_k<2><<<(EE + 7) / 8, 256, SMEM_STEP>>>(Wi2, bi2, Wh2, bh2, t);
    }

    // decoder: [8192,400] @ decW^T + decb  (N=10000)
    {
        dim3 g((VV + 63) / 64, NROW / 64);
        sgemm_nt<1><<<g, 256>>>(nullptr, nullptr, decW, decb, out, VV);
    }

    finalize_states<<<(HH * BB + 255) / 256, 256>>>(out);
}

// round 7
// speedup vs baseline: 1.7207x; 1.0047x over previous
#include <cuda_runtime.h>
#include <cuda_bf16.h>
#include <math.h>

#define EE   400
#define HH   1150
#define VV   10000
#define TT   256
#define BB   32
#define M4H  4600
#define NROW 8192

typedef unsigned long long ull;

// ---- device scratch (static; no allocations allowed) ----
__device__ __align__(16) float g_P0[(size_t)NROW * M4H];   // emb@Wi0^T + b0
__device__ __align__(16) float g_h2all[(size_t)NROW * EE]; // layer2 h per step
__device__ __align__(16) float g_h0[2][HH * BB];           // [k][b], ping-pong
__device__ __align__(16) float g_h1[2][HH * BB];
__device__ __align__(16) float g_h2[2][EE * BB];
__device__ __align__(16) float g_c0s[HH * BB];
__device__ __align__(16) float g_c1s[HH * BB];
__device__ __align__(16) float g_c2s[EE * BB];

// ---- f32x2 helpers ----
__device__ __forceinline__ void fma2(ull& d, ull a, ull b) {
    asm("fma.rn.f32x2 %0, %1, %2, %0;" : "+l"(d) : "l"(a), "l"(b));
}
__device__ __forceinline__ ull dup2(float x) {
    ull r; asm("mov.b64 %0, {%1, %2};" : "=l"(r) : "f"(x), "f"(x)); return r;
}
__device__ __forceinline__ float2 unp2(ull v) {
    float2 r; asm("mov.b64 {%0, %1}, %2;" : "=f"(r.x), "=f"(r.y) : "l"(v)); return r;
}

// =======================================================================
// SGEMM: C[M,N] = A[M,400] * Bm[N,400]^T + bias.  64x64 tile, 256 threads.
// MODE 0: A rows gathered via gidx (embedding), C = g_P0.
// MODE 1: A = g_h2all, C = Cout (decoder output).
// =======================================================================
template<int MODE>
__global__ __launch_bounds__(256) void sgemm_nt(
    const float* __restrict__ A, const int* __restrict__ gidx,
    const float* __restrict__ Bm, const float* __restrict__ bias,
    float* __restrict__ Cout, int N)
{
    const int K = EE;
    __shared__ __align__(16) float As[16][68];
    __shared__ __align__(16) float Bs[16][68];

    float* C = (MODE == 0) ? g_P0 : Cout;
    const float* Abase = (MODE == 1) ? g_h2all : A;

    const int tid = threadIdx.x;
    const int bm = blockIdx.y * 64;
    const int bn = blockIdx.x * 64;

    const int r = tid >> 2, q = tid & 3;
    const float* arow = (MODE == 0)
        ? Abase + (size_t)gidx[bm + r] * K
        : Abase + (size_t)(bm + r) * K;
    const int nrow = bn + r;
    const bool bok = nrow < N;
    const float* brow = Bm + (size_t)(bok ? nrow : (N - 1)) * K;

    const int tx = tid & 15, ty = tid >> 4;

    ull acc[4][2];
#pragma unroll
    for (int i = 0; i < 4; ++i) { acc[i][0] = 0ull; acc[i][1] = 0ull; }

    for (int kc = 0; kc < K; kc += 16) {
        float4 av = *(const float4*)(arow + kc + q * 4);
        float4 bv = *(const float4*)(brow + kc + q * 4);
        if (!bok) { bv.x = 0.f; bv.y = 0.f; bv.z = 0.f; bv.w = 0.f; }
        __syncthreads();
        As[q*4+0][r] = av.x; As[q*4+1][r] = av.y; As[q*4+2][r] = av.z; As[q*4+3][r] = av.w;
        Bs[q*4+0][r] = bv.x; Bs[q*4+1][r] = bv.y; Bs[q*4+2][r] = bv.z; Bs[q*4+3][r] = bv.w;
        __syncthreads();
#pragma unroll
        for (int k = 0; k < 16; ++k) {
            ull b0 = *(const ull*)&Bs[k][tx*4];
            ull b1 = *(const ull*)&Bs[k][tx*4+2];
            float4 a4 = *(const float4*)&As[k][ty*4];
            ull a;
            a = dup2(a4.x); fma2(acc[0][0], a, b0); fma2(acc[0][1], a, b1);
            a = dup2(a4.y); fma2(acc[1][0], a, b0); fma2(acc[1][1], a, b1);
            a = dup2(a4.z); fma2(acc[2][0], a, b0); fma2(acc[2][1], a, b1);
            a = dup2(a4.w); fma2(acc[3][0], a, b0); fma2(acc[3][1], a, b1);
        }
    }

#pragma unroll
    for (int i = 0; i < 4; ++i) {
        int row = bm + ty * 4 + i;
        float2 c0 = unp2(acc[i][0]);
        float2 c1 = unp2(acc[i][1]);
        float v[4] = {c0.x, c0.y, c1.x, c1.y};
#pragma unroll
        for (int j = 0; j < 4; ++j) {
            int col = bn + tx * 4 + j;
            if (col < N) C[(size_t)row * N + col] = v[j] + bias[col];
        }
    }
}

// =======================================================================
// LSTM step kernel v4: 16 warps (4/SMSP), warp-private K-slices, no
// cross-warp barriers in the mainloop. Output tile 32 rows x 32 batches.
// Warp w handles k-tiles (KT=16) tl = w, w+16, ..., double-buffered in its
// private 12KB smem slice. Lane = (rg 0..7, bg 0..3); thread tile 4 rows x
// 4 batch-pairs = 16 f32x2 accumulators. Partial tiles from the 16 warps
// are staged in a reduction buffer that ALIASES the warp slices (safe:
// written only after __syncthreads when the mainloop is done), then the
// fused LSTM pointwise runs on threads 0..255.
// =======================================================================
#define KT        16
#define NWARP     16
#define WSLICE    12288                   // per-warp: Wd 2*4KB + xs 2*2KB
#define SMEM_STEP (NWARP * WSLICE)        // 196608 (192KB)

struct WarpCtx {
    ull*   Wd;     // [2][KT][32] ull
    float* xs;     // [2][KT][32] float
    int lane, rg, bg;
    bool wok;
};

template<int OUT>
__device__ __forceinline__ void phase_accum(
    const float* __restrict__ W, const float* __restrict__ xsrc, int K,
    int j0, int w, const WarpCtx& C, ull acc[4][4])
{
    const int ntiles = (K + KT - 1) / KT;
    const int gate = C.lane >> 3, jj = C.lane & 7;
    const float* wrow = W + (size_t)(gate * OUT + (C.wok ? (j0 + jj) : 0)) * K;

    float2 wv[8];
    float4 xv[4];

    auto load_regs = [&](int tl) {
        const int k0 = tl * KT;
#pragma unroll
        for (int c = 0; c < 8; ++c) {
            const int kk = k0 + c * 2;
            float2 v;
            if (C.wok && kk + 1 < K) v = *(const float2*)(wrow + kk);
            else {
                v.x = (C.wok && kk < K) ? wrow[kk] : 0.f;
                v.y = 0.f;
            }
            wv[c] = v;
        }
#pragma unroll
        for (int c = 0; c < 4; ++c) {
            const int f = C.lane + 32 * c;
            const int k = k0 + (f >> 3);
            xv[c] = (k < K) ? *(const float4*)(xsrc + (size_t)k * 32 + (f & 7) * 4)
                            : make_float4(0.f, 0.f, 0.f, 0.f);
        }
    };
    auto store_buf = [&](int buf) {
        ull*   wd = C.Wd + buf * (KT * 32);
        float* xd = C.xs + buf * (KT * 32);
#pragma unroll
        for (int c = 0; c < 8; ++c) {
            wd[(c * 2    ) * 32 + C.lane] = dup2(wv[c].x);
            wd[(c * 2 + 1) * 32 + C.lane] = dup2(wv[c].y);
        }
#pragma unroll
        for (int c = 0; c < 4; ++c) {
            const int f = C.lane + 32 * c;
            *(float4*)(xd + (f >> 3) * 32 + (f & 7) * 4) = xv[c];
        }
    };

    load_regs(w);
    store_buf(0);
    __syncwarp();

    int cur = 0;
    for (int tl = w; tl < ntiles; tl += NWARP) {
        const bool more = (tl + NWARP) < ntiles;
        if (more) load_regs(tl + NWARP);

        const ull*   bw = C.Wd + cur * (KT * 32);
        const float* bx = C.xs + cur * (KT * 32);
#pragma unroll
        for (int k = 0; k < KT; ++k) {
            ulonglong2 w01 = *(const ulonglong2*)(bw + k * 32 + C.rg * 4);
            ulonglong2 w23 = *(const ulonglong2*)(bw + k * 32 + C.rg * 4 + 2);
            ulonglong2 x01 = *(const ulonglong2*)(bx + k * 32 + C.bg * 8);
            ulonglong2 x23 = *(const ulonglong2*)(bx + k * 32 + C.bg * 8 + 4);
            fma2(acc[0][0], w01.x, x01.x); fma2(acc[0][1], w01.x, x01.y);
            fma2(acc[0][2], w01.x, x23.x); fma2(acc[0][3], w01.x, x23.y);
            fma2(acc[1][0], w01.y, x01.x); fma2(acc[1][1], w01.y, x01.y);
            fma2(acc[1][2], w01.y, x23.x); fma2(acc[1][3], w01.y, x23.y);
            fma2(acc[2][0], w23.x, x01.x); fma2(acc[2][1], w23.x, x01.y);
            fma2(acc[2][2], w23.x, x23.x); fma2(acc[2][3], w23.x, x23.y);
            fma2(acc[3][0], w23.y, x01.x); fma2(acc[3][1], w23.y, x01.y);
            fma2(acc[3][2], w23.y, x23.x); fma2(acc[3][3], w23.y, x23.y);
        }
        if (more) store_buf(cur ^ 1);
        __syncwarp();
        cur ^= 1;
    }
}

template<int LAYER>
__global__ __launch_bounds__(512) void lstm_step_k(
    const float* __restrict__ Wx, const float* __restrict__ bx,
    const float* __restrict__ Wh, const float* __restrict__ bh,
    int t)
{
    constexpr int OUT = (LAYER == 2) ? EE : HH;
    constexpr int KH  = (LAYER == 2) ? EE : HH;

    extern __shared__ __align__(16) char smem[];
    const int tid  = threadIdx.x;
    const int w    = tid >> 5;
    const int lane = tid & 31;
    const int j0   = blockIdx.x * 8;
    const int par  = t & 1;

    WarpCtx C;
    C.Wd = (ull*)(smem + w * WSLICE);
    C.xs = (float*)(smem + w * WSLICE + 8192);
    C.lane = lane;
    C.rg = lane >> 2;
    C.bg = lane & 3;
    C.wok = (j0 + (lane & 7)) < OUT;
    float* red = (float*)smem;   // [16][32][32] floats, aliases warp slices

    const float* xin  = (LAYER == 1) ? g_h0[par ^ 1]
                      : (LAYER == 2) ? g_h1[par ^ 1] : nullptr;
    const float* hold = (LAYER == 0) ? g_h0[par]
                      : (LAYER == 1) ? g_h1[par] : g_h2[par];
    float* hnew = (LAYER == 0) ? g_h0[par ^ 1]
                : (LAYER == 1) ? g_h1[par ^ 1] : g_h2[par ^ 1];
    float* cst  = (LAYER == 0) ? g_c0s : (LAYER == 1) ? g_c1s : g_c2s;

    ull acc[4][4];
#pragma unroll
    for (int r = 0; r < 4; ++r)
#pragma unroll
        for (int i = 0; i < 4; ++i) acc[r][i] = 0ull;

    if (LAYER != 0) phase_accum<OUT>(Wx, xin, HH, j0, w, C, acc);
    phase_accum<OUT>(Wh, hold, KH, j0, w, C, acc);

    // ---- all mainloops done; stage 16 partial tiles (aliases slices) ----
    __syncthreads();
    float* redw = red + w * 1024;
#pragma unroll
    for (int r = 0; r < 4; ++r) {
        const int row = C.rg * 4 + r;
        ulonglong2 p0; p0.x = acc[r][0]; p0.y = acc[r][1];
        ulonglong2 p1; p1.x = acc[r][2]; p1.y = acc[r][3];
        *(ulonglong2*)(redw + row * 32 + C.bg * 8)     = p0;
        *(ulonglong2*)(redw + row * 32 + C.bg * 8 + 4) = p1;
    }
    __syncthreads();

    // ---- reduce + fused LSTM pointwise: threads 0..255 = (jj, b) ----
    if (tid < 256) {
        const int jj = tid >> 5, b = tid & 31;
        const int j = j0 + jj;
        if (j < OUT) {
            float pre[4];
#pragma unroll
            for (int gate = 0; gate < 4; ++gate) {
                const int row = gate * 8 + jj;
                float s = 0.f;
#pragma unroll
                for (int ww = 0; ww < NWARP; ++ww)
                    s += red[ww * 1024 + row * 32 + b];
                pre[gate] = s;
            }
            float ip, fp, op, gp;
            if (LAYER == 0) {
                const float* p = g_P0 + (size_t)(t * 32 + b) * M4H + j;
                ip = pre[0] + p[0]      + bh[j];
                fp = pre[1] + p[HH]     + bh[HH + j];
                op = pre[2] + p[2 * HH] + bh[2 * HH + j];
                gp = pre[3] + p[3 * HH] + bh[3 * HH + j];
            } else {
                ip = pre[0] + bx[j]           + bh[j];
                fp = pre[1] + bx[OUT + j]     + bh[OUT + j];
                op = pre[2] + bx[2 * OUT + j] + bh[2 * OUT + j];
                gp = pre[3] + bx[3 * OUT + j] + bh[3 * OUT + j];
            }
            const float gi = 1.f / (1.f + expf(-ip));
            const float gf = 1.f / (1.f + expf(-fp));
            const float go = 1.f / (1.f + expf(-op));
            const float gg = tanhf(gp);
            const float cn = gf * cst[j * 32 + b] + gi * gg;
            cst[j * 32 + b] = cn;
            const float hv = go * tanhf(cn);
            hnew[j * 32 + b] = hv;
            if (LAYER == 2)
                g_h2all[(size_t)(t * 32 + b) * EE + j] = hv;
        }
    }
}

// ---- init: transpose harness states into [k][b] buffers ----
__global__ void init_states(const float* __restrict__ h0,
                            const float* __restrict__ c0,
                            const float* __restrict__ h0l,
                            const float* __restrict__ c0l)
{
    int idx = blockIdx.x * blockDim.x + threadIdx.x;
    if (idx < HH * BB) {
        int k = idx >> 5, b = idx & 31;
        g_h0[0][idx] = h0[b * HH + k];
        g_c0s[idx]   = c0[b * HH + k];
        g_h1[0][idx] = h0[BB * HH + b * HH + k];
        g_c1s[idx]   = c0[BB * HH + b * HH + k];
    }
    if (idx < EE * BB) {
        int k = idx >> 5, b = idx & 31;
        g_h2[0][idx] = h0l[b * EE + k];
        g_c2s[idx]   = c0l[b * EE + k];
    }
}

// ---- finalize: write state outputs after decoded block ----
__global__ void finalize_states(float* __restrict__ out)
{
    const size_t D1 = (size_t)TT * BB * VV;       // hf0 [2,B,H]
    const size_t D2 = D1 + 2 * BB * HH;           // hf1 [B,E]
    const size_t D3 = D2 + BB * EE;               // cf0 [2,B,H]
    const size_t D4 = D3 + 2 * BB * HH;           // cf1 [B,E]
    int idx = blockIdx.x * blockDim.x + threadIdx.x;
    if (idx < HH * BB) {
        int k = idx >> 5, b = idx & 31;
        out[D1 + b * HH + k]            = g_h0[0][idx];
        out[D1 + BB * HH + b * HH + k]  = g_h1[0][idx];
        out[D3 + b * HH + k]            = g_c0s[idx];
        out[D3 + BB * HH + b * HH + k]  = g_c1s[idx];
    }
    if (idx < EE * BB) {
        int k = idx >> 5, b = idx & 31;
        out[D2 + b * EE + k] = g_h2[0][idx];
        out[D4 + b * EE + k] = g_c2s[idx];
    }
}

// =======================================================================
extern "C" void kernel_launch(void* const* d_in, const int* in_sizes, int n_in,
                              void* d_out, int out_size)
{
    const int*   x    = (const int*)  d_in[0];
    const float* h0   = (const float*)d_in[1];
    const float* c0   = (const float*)d_in[2];
    const float* h0l  = (const float*)d_in[3];
    const float* c0l  = (const float*)d_in[4];
    const float* emb  = (const float*)d_in[5];
    const float* Wi0  = (const float*)d_in[6];
    const float* bi0  = (const float*)d_in[7];
    const float* Wh0  = (const float*)d_in[8];
    const float* bh0  = (const float*)d_in[9];
    const float* Wi1  = (const float*)d_in[10];
    const float* bi1  = (const float*)d_in[11];
    const float* Wh1  = (const float*)d_in[12];
    const float* bh1  = (const float*)d_in[13];
    const float* Wi2  = (const float*)d_in[14];
    const float* bi2  = (const float*)d_in[15];
    const float* Wh2  = (const float*)d_in[16];
    const float* bh2  = (const float*)d_in[17];
    const float* decW = (const float*)d_in[18];
    const float* decb = (const float*)d_in[19];
    float* out = (float*)d_out;

    cudaFuncSetAttribute(lstm_step_k<0>, cudaFuncAttributeMaxDynamicSharedMemorySize, SMEM_STEP);
    cudaFuncSetAttribute(lstm_step_k<1>, cudaFuncAttributeMaxDynamicSharedMemorySize, SMEM_STEP);
    cudaFuncSetAttribute(lstm_step_k<2>, cudaFuncAttributeMaxDynamicSharedMemorySize, SMEM_STEP);

    init_states<<<(HH * BB + 255) / 256, 256>>>(h0, c0, h0l, c0l);

    // P0 = emb[x] @ Wi0^T + bi0   (M=8192, N=4600, K=400)
    {
        dim3 g((M4H + 63) / 64, NROW / 64);
        sgemm_nt<0><<<g, 256>>>(emb, x, Wi0, bi0, nullptr, M4H);
    }

    // recurrence: 256 steps x 3 layers
    for (int t = 0; t < TT; ++t) {
        lstm_step_k<0><<<(HH + 7) / 8, 512, SMEM_STEP>>>(nullptr, nullptr, Wh0, bh0, t);
        lstm_step_k<1><<<(HH + 7) / 8, 512, SMEM_STEP>>>(Wi1, bi1, Wh1, bh1, t);
        lstm_step_k<2><<<(EE + 7) / 8, 512, SMEM_STEP>>>(Wi2, bi2, Wh2, bh2, t);
    }

    // decoder: [8192,400] @ decW^T + decb  (N=10000)
    {
        dim3 g((VV + 63) / 64, NROW / 64);
        sgemm_nt<1><<<g, 256>>>(nullptr, nullptr, decW, decb, out, VV);
    }

    finalize_states<<<(HH * BB + 255) / 256, 256>>>(out);
}

// round 8
// speedup vs baseline: 1.7239x; 1.0019x over previous
#include <cuda_runtime.h>
#include <cuda_bf16.h>
#include <math.h>

#define EE   400
#define HH   1150
#define VV   10000
#define TT   256
#define BB   32
#define M4H  4600
#define NROW 8192

typedef unsigned long long ull;

// ---- device scratch (static; no allocations allowed) ----
__device__ __align__(16) float g_P0[(size_t)NROW * M4H];   // emb@Wi0^T + b0
__device__ __align__(16) float g_h2all[(size_t)NROW * EE]; // layer2 h per step
__device__ __align__(16) float g_h0[2][HH * BB];           // [k][b], ping-pong
__device__ __align__(16) float g_h1[2][HH * BB];
__device__ __align__(16) float g_h2[2][EE * BB];
__device__ __align__(16) float g_c0s[HH * BB];
__device__ __align__(16) float g_c1s[HH * BB];
__device__ __align__(16) float g_c2s[EE * BB];

// ---- f32x2 helpers ----
__device__ __forceinline__ void fma2(ull& d, ull a, ull b) {
    asm("fma.rn.f32x2 %0, %1, %2, %0;" : "+l"(d) : "l"(a), "l"(b));
}
__device__ __forceinline__ ull dup2(float x) {
    ull r; asm("mov.b64 %0, {%1, %2};" : "=l"(r) : "f"(x), "f"(x)); return r;
}
__device__ __forceinline__ float2 unp2(ull v) {
    float2 r; asm("mov.b64 {%0, %1}, %2;" : "=f"(r.x), "=f"(r.y) : "l"(v)); return r;
}

// =======================================================================
// SGEMM: C[M,N] = A[M,400] * Bm[N,400]^T + bias.  64x64 tile, 256 threads.
// MODE 0: A rows gathered via gidx (embedding), C = g_P0.
// MODE 1: A = g_h2all, C = Cout (decoder output).
// =======================================================================
template<int MODE>
__global__ __launch_bounds__(256) void sgemm_nt(
    const float* __restrict__ A, const int* __restrict__ gidx,
    const float* __restrict__ Bm, const float* __restrict__ bias,
    float* __restrict__ Cout, int N)
{
    const int K = EE;
    __shared__ __align__(16) float As[16][68];
    __shared__ __align__(16) float Bs[16][68];

    float* C = (MODE == 0) ? g_P0 : Cout;
    const float* Abase = (MODE == 1) ? g_h2all : A;

    const int tid = threadIdx.x;
    const int bm = blockIdx.y * 64;
    const int bn = blockIdx.x * 64;

    const int r = tid >> 2, q = tid & 3;
    const float* arow = (MODE == 0)
        ? Abase + (size_t)gidx[bm + r] * K
        : Abase + (size_t)(bm + r) * K;
    const int nrow = bn + r;
    const bool bok = nrow < N;
    const float* brow = Bm + (size_t)(bok ? nrow : (N - 1)) * K;

    const int tx = tid & 15, ty = tid >> 4;

    ull acc[4][2];
#pragma unroll
    for (int i = 0; i < 4; ++i) { acc[i][0] = 0ull; acc[i][1] = 0ull; }

    for (int kc = 0; kc < K; kc += 16) {
        float4 av = *(const float4*)(arow + kc + q * 4);
        float4 bv = *(const float4*)(brow + kc + q * 4);
        if (!bok) { bv.x = 0.f; bv.y = 0.f; bv.z = 0.f; bv.w = 0.f; }
        __syncthreads();
        As[q*4+0][r] = av.x; As[q*4+1][r] = av.y; As[q*4+2][r] = av.z; As[q*4+3][r] = av.w;
        Bs[q*4+0][r] = bv.x; Bs[q*4+1][r] = bv.y; Bs[q*4+2][r] = bv.z; Bs[q*4+3][r] = bv.w;
        __syncthreads();
#pragma unroll
        for (int k = 0; k < 16; ++k) {
            ull b0 = *(const ull*)&Bs[k][tx*4];
            ull b1 = *(const ull*)&Bs[k][tx*4+2];
            float4 a4 = *(const float4*)&As[k][ty*4];
            ull a;
            a = dup2(a4.x); fma2(acc[0][0], a, b0); fma2(acc[0][1], a, b1);
            a = dup2(a4.y); fma2(acc[1][0], a, b0); fma2(acc[1][1], a, b1);
            a = dup2(a4.z); fma2(acc[2][0], a, b0); fma2(acc[2][1], a, b1);
            a = dup2(a4.w); fma2(acc[3][0], a, b0); fma2(acc[3][1], a, b1);
        }
    }

#pragma unroll
    for (int i = 0; i < 4; ++i) {
        int row = bm + ty * 4 + i;
        float2 c0 = unp2(acc[i][0]);
        float2 c1 = unp2(acc[i][1]);
        float v[4] = {c0.x, c0.y, c1.x, c1.y};
#pragma unroll
        for (int j = 0; j < 4; ++j) {
            int col = bn + tx * 4 + j;
            if (col < N) C[(size_t)row * N + col] = v[j] + bias[col];
        }
    }
}

// =======================================================================
// LSTM step kernel v4: 16 warps (4/SMSP), warp-private K-slices, no
// cross-warp barriers in the mainloop. Output tile 32 rows x 32 batches.
// Warp w handles k-tiles (KT=16) tl = w, w+16, ..., double-buffered in its
// private 12KB smem slice. Lane = (rg 0..7, bg 0..3); thread tile 4 rows x
// 4 batch-pairs = 16 f32x2 accumulators. Partial tiles from the 16 warps
// are staged in a reduction buffer that ALIASES the warp slices (safe:
// written only after __syncthreads when the mainloop is done), then the
// fused LSTM pointwise runs on threads 0..255.
// =======================================================================
#define KT        16
#define NWARP     16
#define WSLICE    12288                   // per-warp: Wd 2*4KB + xs 2*2KB
#define SMEM_STEP (NWARP * WSLICE)        // 196608 (192KB)

struct WarpCtx {
    ull*   Wd;     // [2][KT][32] ull
    float* xs;     // [2][KT][32] float
    int lane, rg, bg;
    bool wok;
};

template<int OUT>
__device__ __forceinline__ void phase_accum(
    const float* __restrict__ W, const float* __restrict__ xsrc, int K,
    int j0, int w, const WarpCtx& C, ull acc[4][4])
{
    const int ntiles = (K + KT - 1) / KT;
    const int gate = C.lane >> 3, jj = C.lane & 7;
    const float* wrow = W + (size_t)(gate * OUT + (C.wok ? (j0 + jj) : 0)) * K;

    float2 wv[8];
    float4 xv[4];

    auto load_regs = [&](int tl) {
        const int k0 = tl * KT;
#pragma unroll
        for (int c = 0; c < 8; ++c) {
            const int kk = k0 + c * 2;
            float2 v;
            if (C.wok && kk + 1 < K) v = *(const float2*)(wrow + kk);
            else {
                v.x = (C.wok && kk < K) ? wrow[kk] : 0.f;
                v.y = 0.f;
            }
            wv[c] = v;
        }
#pragma unroll
        for (int c = 0; c < 4; ++c) {
            const int f = C.lane + 32 * c;
            const int k = k0 + (f >> 3);
            xv[c] = (k < K) ? *(const float4*)(xsrc + (size_t)k * 32 + (f & 7) * 4)
                            : make_float4(0.f, 0.f, 0.f, 0.f);
        }
    };
    auto store_buf = [&](int buf) {
        ull*   wd = C.Wd + buf * (KT * 32);
        float* xd = C.xs + buf * (KT * 32);
#pragma unroll
        for (int c = 0; c < 8; ++c) {
            wd[(c * 2    ) * 32 + C.lane] = dup2(wv[c].x);
            wd[(c * 2 + 1) * 32 + C.lane] = dup2(wv[c].y);
        }
#pragma unroll
        for (int c = 0; c < 4; ++c) {
            const int f = C.lane + 32 * c;
            *(float4*)(xd + (f >> 3) * 32 + (f & 7) * 4) = xv[c];
        }
    };

    load_regs(w);
    store_buf(0);
    __syncwarp();

    int cur = 0;
    for (int tl = w; tl < ntiles; tl += NWARP) {
        const bool more = (tl + NWARP) < ntiles;
        if (more) load_regs(tl + NWARP);

        const ull*   bw = C.Wd + cur * (KT * 32);
        const float* bx = C.xs + cur * (KT * 32);
#pragma unroll
        for (int k = 0; k < KT; ++k) {
            ulonglong2 w01 = *(const ulonglong2*)(bw + k * 32 + C.rg * 4);
            ulonglong2 w23 = *(const ulonglong2*)(bw + k * 32 + C.rg * 4 + 2);
            ulonglong2 x01 = *(const ulonglong2*)(bx + k * 32 + C.bg * 8);
            ulonglong2 x23 = *(const ulonglong2*)(bx + k * 32 + C.bg * 8 + 4);
            fma2(acc[0][0], w01.x, x01.x); fma2(acc[0][1], w01.x, x01.y);
            fma2(acc[0][2], w01.x, x23.x); fma2(acc[0][3], w01.x, x23.y);
            fma2(acc[1][0], w01.y, x01.x); fma2(acc[1][1], w01.y, x01.y);
            fma2(acc[1][2], w01.y, x23.x); fma2(acc[1][3], w01.y, x23.y);
            fma2(acc[2][0], w23.x, x01.x); fma2(acc[2][1], w23.x, x01.y);
            fma2(acc[2][2], w23.x, x23.x); fma2(acc[2][3], w23.x, x23.y);
            fma2(acc[3][0], w23.y, x01.x); fma2(acc[3][1], w23.y, x01.y);
            fma2(acc[3][2], w23.y, x23.x); fma2(acc[3][3], w23.y, x23.y);
        }
        if (more) store_buf(cur ^ 1);
        __syncwarp();
        cur ^= 1;
    }
}

template<int LAYER>
__global__ __launch_bounds__(512) void lstm_step_k(
    const float* __restrict__ Wx, const float* __restrict__ bx,
    const float* __restrict__ Wh, const float* __restrict__ bh,
    int t)
{
    constexpr int OUT = (LAYER == 2) ? EE : HH;
    constexpr int KH  = (LAYER == 2) ? EE : HH;

    extern __shared__ __align__(16) char smem[];
    const int tid  = threadIdx.x;
    const int w    = tid >> 5;
    const int lane = tid & 31;
    const int j0   = blockIdx.x * 8;
    const int par  = t & 1;

    WarpCtx C;
    C.Wd = (ull*)(smem + w * WSLICE);
    C.xs = (float*)(smem + w * WSLICE + 8192);
    C.lane = lane;
    C.rg = lane >> 2;
    C.bg = lane & 3;
    C.wok = (j0 + (lane & 7)) < OUT;
    float* red = (float*)smem;   // [16][32][32] floats, aliases warp slices

    const float* xin  = (LAYER == 1) ? g_h0[par ^ 1]
                      : (LAYER == 2) ? g_h1[par ^ 1] : nullptr;
    const float* hold = (LAYER == 0) ? g_h0[par]
                      : (LAYER == 1) ? g_h1[par] : g_h2[par];
    float* hnew = (LAYER == 0) ? g_h0[par ^ 1]
                : (LAYER == 1) ? g_h1[par ^ 1] : g_h2[par ^ 1];
    float* cst  = (LAYER == 0) ? g_c0s : (LAYER == 1) ? g_c1s : g_c2s;

    ull acc[4][4];
#pragma unroll
    for (int r = 0; r < 4; ++r)
#pragma unroll
        for (int i = 0; i < 4; ++i) acc[r][i] = 0ull;

    if (LAYER != 0) phase_accum<OUT>(Wx, xin, HH, j0, w, C, acc);
    phase_accum<OUT>(Wh, hold, KH, j0, w, C, acc);

    // ---- all mainloops done; stage 16 partial tiles (aliases slices) ----
    __syncthreads();
    float* redw = red + w * 1024;
#pragma unroll
    for (int r = 0; r < 4; ++r) {
        const int row = C.rg * 4 + r;
        ulonglong2 p0; p0.x = acc[r][0]; p0.y = acc[r][1];
        ulonglong2 p1; p1.x = acc[r][2]; p1.y = acc[r][3];
        *(ulonglong2*)(redw + row * 32 + C.bg * 8)     = p0;
        *(ulonglong2*)(redw + row * 32 + C.bg * 8 + 4) = p1;
    }
    __syncthreads();

    // ---- reduce + fused LSTM pointwise: threads 0..255 = (jj, b) ----
    if (tid < 256) {
        const int jj = tid >> 5, b = tid & 31;
        const int j = j0 + jj;
        if (j < OUT) {
            float pre[4];
#pragma unroll
            for (int gate = 0; gate < 4; ++gate) {
                const int row = gate * 8 + jj;
                float s = 0.f;
#pragma unroll
                for (int ww = 0; ww < NWARP; ++ww)
                    s += red[ww * 1024 + row * 32 + b];
                pre[gate] = s;
            }
            float ip, fp, op, gp;
            if (LAYER == 0) {
                const float* p = g_P0 + (size_t)(t * 32 + b) * M4H + j;
                ip = pre[0] + p[0]      + bh[j];
                fp = pre[1] + p[HH]     + bh[HH + j];
                op = pre[2] + p[2 * HH] + bh[2 * HH + j];
                gp = pre[3] + p[3 * HH] + bh[3 * HH + j];
            } else {
                ip = pre[0] + bx[j]           + bh[j];
                fp = pre[1] + bx[OUT + j]     + bh[OUT + j];
                op = pre[2] + bx[2 * OUT + j] + bh[2 * OUT + j];
                gp = pre[3] + bx[3 * OUT + j] + bh[3 * OUT + j];
            }
            const float gi = 1.f / (1.f + expf(-ip));
            const float gf = 1.f / (1.f + expf(-fp));
            const float go = 1.f / (1.f + expf(-op));
            const float gg = tanhf(gp);
            const float cn = gf * cst[j * 32 + b] + gi * gg;
            cst[j * 32 + b] = cn;
            const float hv = go * tanhf(cn);
            hnew[j * 32 + b] = hv;
            if (LAYER == 2)
                g_h2all[(size_t)(t * 32 + b) * EE + j] = hv;
        }
    }
}

// ---- init: transpose harness states into [k][b] buffers ----
__global__ void init_states(const float* __restrict__ h0,
                            const float* __restrict__ c0,
                            const float* __restrict__ h0l,
                            const float* __restrict__ c0l)
{
    int idx = blockIdx.x * blockDim.x + threadIdx.x;
    if (idx < HH * BB) {
        int k = idx >> 5, b = idx & 31;
        g_h0[0][idx] = h0[b * HH + k];
        g_c0s[idx]   = c0[b * HH + k];
        g_h1[0][idx] = h0[BB * HH + b * HH + k];
        g_c1s[idx]   = c0[BB * HH + b * HH + k];
    }
    if (idx < EE * BB) {
        int k = idx >> 5, b = idx & 31;
        g_h2[0][idx] = h0l[b * EE + k];
        g_c2s[idx]   = c0l[b * EE + k];
    }
}

// ---- finalize: write state outputs after decoded block ----
__global__ void finalize_states(float* __restrict__ out)
{
    const size_t D1 = (size_t)TT * BB * VV;       // hf0 [2,B,H]
    const size_t D2 = D1 + 2 * BB * HH;           // hf1 [B,E]
    const size_t D3 = D2 + BB * EE;               // cf0 [2,B,H]
    const size_t D4 = D3 + 2 * BB * HH;           // cf1 [B,E]
    int idx = blockIdx.x * blockDim.x + threadIdx.x;
    if (idx < HH * BB) {
        int k = idx >> 5, b = idx & 31;
        out[D1 + b * HH + k]            = g_h0[0][idx];
        out[D1 + BB * HH + b * HH + k]  = g_h1[0][idx];
        out[D3 + b * HH + k]            = g_c0s[idx];
        out[D3 + BB * HH + b * HH + k]  = g_c1s[idx];
    }
    if (idx < EE * BB) {
        int k = idx >> 5, b = idx & 31;
        out[D2 + b * EE + k] = g_h2[0][idx];
        out[D4 + b * EE + k] = g_c2s[idx];
    }
}

// =======================================================================
extern "C" void kernel_launch(void* const* d_in, const int* in_sizes, int n_in,
                              void* d_out, int out_size)
{
    const int*   x    = (const int*)  d_in[0];
    const float* h0   = (const float*)d_in[1];
    const float* c0   = (const float*)d_in[2];
    const float* h0l  = (const float*)d_in[3];
    const float* c0l  = (const float*)d_in[4];
    const float* emb  = (const float*)d_in[5];
    const float* Wi0  = (const float*)d_in[6];
    const float* bi0  = (const float*)d_in[7];
    const float* Wh0  = (const float*)d_in[8];
    const float* bh0  = (const float*)d_in[9];
    const float* Wi1  = (const float*)d_in[10];
    const float* bi1  = (const float*)d_in[11];
    const float* Wh1  = (const float*)d_in[12];
    const float* bh1  = (const float*)d_in[13];
    const float* Wi2  = (const float*)d_in[14];
    const float* bi2  = (const float*)d_in[15];
    const float* Wh2  = (const float*)d_in[16];
    const float* bh2  = (const float*)d_in[17];
    const float* decW = (const float*)d_in[18];
    const float* decb = (const float*)d_in[19];
    float* out = (float*)d_out;

    cudaFuncSetAttribute(lstm_step_k<0>, cudaFuncAttributeMaxDynamicSharedMemorySize, SMEM_STEP);
    cudaFuncSetAttribute(lstm_step_k<1>, cudaFuncAttributeMaxDynamicSharedMemorySize, SMEM_STEP);
    cudaFuncSetAttribute(lstm_step_k<2>, cudaFuncAttributeMaxDynamicSharedMemorySize, SMEM_STEP);

    init_states<<<(HH * BB + 255) / 256, 256>>>(h0, c0, h0l, c0l);

    // P0 = emb[x] @ Wi0^T + bi0   (M=8192, N=4600, K=400)
    {
        dim3 g((M4H + 63) / 64, NROW / 64);
        sgemm_nt<0><<<g, 256>>>(emb, x, Wi0, bi0, nullptr, M4H);
    }

    // recurrence: 256 steps x 3 layers
    for (int t = 0; t < TT; ++t) {
        lstm_step_k<0><<<(HH + 7) / 8, 512, SMEM_STEP>>>(nullptr, nullptr, Wh0, bh0, t);
        lstm_step_k<1><<<(HH + 7) / 8, 512, SMEM_STEP>>>(Wi1, bi1, Wh1, bh1, t);
        lstm_step_k<2><<<(EE + 7) / 8, 512, SMEM_STEP>>>(Wi2, bi2, Wh2, bh2, t);
    }

    // decoder: [8192,400] @ decW^T + decb  (N=10000)
    {
        dim3 g((VV + 63) / 64, NROW / 64);
        sgemm_nt<1><<<g, 256>>>(nullptr, nullptr, decW, decb, out, VV);
    }

    finalize_states<<<(HH * BB + 255) / 256, 256>>>(out);
}

// round 11
// speedup vs baseline: 2.4031x; 1.3940x over previous
#include <cuda_runtime.h>
#include <cuda_bf16.h>
#include <math.h>
#include <stdint.h>

#define EE   400
#define HH   1150
#define VV   10000
#define TT   256
#define BB   32
#define M4H  4600
#define NROW 8192
typedef unsigned long long ull;

template<int L> struct LC;
template<> struct LC<0>{ enum{OUT=1150,NJB=36,NCH=18,S=4,KX=0,   KH=1150}; };
template<> struct LC<1>{ enum{OUT=1150,NJB=36,NCH=36,S=4,KX=1150,KH=1150}; };
template<> struct LC<2>{ enum{OUT=400, NJB=13,NCH=25,S=8,KX=1150,KH=400 }; };

// ---------------- device scratch ----------------
__device__ __align__(16) float g_P0[(size_t)NROW * M4H];
__device__ __align__(16) float g_h2all[(size_t)NROW * EE];
__device__ __align__(16) float g_c[3][HH * BB];
__device__ __align__(16) float g_hf[3][HH * BB];
__device__ __align__(16) __nv_bfloat16 gA0[(size_t)36*18*16384];
__device__ __align__(16) __nv_bfloat16 gA1[(size_t)36*36*16384];
__device__ __align__(16) __nv_bfloat16 gA2[(size_t)13*25*16384];
__device__ __align__(16) __nv_bfloat16 gB0[2][18*4096];
__device__ __align__(16) __nv_bfloat16 gB1[2][36*4096];
__device__ __align__(16) __nv_bfloat16 gB2[2][25*4096];
__device__ __align__(16) float gPart0[36*4*4096];
__device__ __align__(16) float gPart1[36*4*4096];
__device__ __align__(16) float gPart2[13*8*4096];
__device__ int g_cnt[3][36];   // zero-init; reset by consumer each launch

template<int L> __device__ __forceinline__ __nv_bfloat16* Apack(){
    return (L==0) ? gA0 : (L==1) ? gA1 : gA2;
}
template<int L> __device__ __forceinline__ __nv_bfloat16* Bpack(int par){
    return (L==0) ? gB0[par] : (L==1) ? gB1[par] : gB2[par];
}
template<int L> __device__ __forceinline__ float* Ppart(){
    return (L==0) ? gPart0 : (L==1) ? gPart1 : gPart2;
}

// ---------------- helpers ----------------
#define SWZ(x) ((x) ^ (((x) >> 3) & 0x70))
__device__ __forceinline__ uint32_t smem_u32(const void* p){
    uint32_t a;
    asm("{ .reg .u64 t; cvta.to.shared.u64 t, %1; cvt.u32.u64 %0, t; }" : "=r"(a) : "l"(p));
    return a;
}
__device__ __forceinline__ void cpa16(uint32_t dst, const void* src){
    asm volatile("cp.async.ca.shared.global [%0], [%1], 16;" :: "r"(dst), "l"(src));
}
#define CPA_COMMIT() asm volatile("cp.async.commit_group;" ::: "memory")

// write one h value as bf16 hi/lo into a preswizzled 32x64 B tile
__device__ __forceinline__ void stageB(__nv_bfloat16* base, int kabs, int b, float v){
    int c = kabs >> 6, kk = kabs & 63;
    uint32_t pos = SWZ((uint32_t)(b*128 + kk*2)) >> 1;
    __nv_bfloat16 h = __float2bfloat16(v);
    base[(size_t)c*4096 + pos]        = h;
    base[(size_t)c*4096 + 2048 + pos] = __float2bfloat16(v - __bfloat162float(h));
}

// f32x2 (for the fp32 GEMMs)
__device__ __forceinline__ void fma2(ull& d, ull a, ull b){
    asm("fma.rn.f32x2 %0, %1, %2, %0;" : "+l"(d) : "l"(a), "l"(b));
}
__device__ __forceinline__ ull dup2(float x){
    ull r; asm("mov.b64 %0, {%1, %2};" : "=l"(r) : "f"(x), "f"(x)); return r;
}
__device__ __forceinline__ float2 unp2(ull v){
    float2 r; asm("mov.b64 {%0, %1}, %2;" : "=f"(r.x), "=f"(r.y) : "l"(v)); return r;
}

// =======================================================================
// fp32 SGEMM (proven): C[M,N] = A[M,400]*Bm[N,400]^T + bias
// =======================================================================
template<int MODE>
__global__ __launch_bounds__(256) void sgemm_nt(
    const float* __restrict__ A, const int* __restrict__ gidx,
    const float* __restrict__ Bm, const float* __restrict__ bias,
    float* __restrict__ Cout, int N)
{
    const int K = EE;
    __shared__ __align__(16) float As[16][68];
    __shared__ __align__(16) float Bs[16][68];
    float* C = (MODE==0) ? g_P0 : Cout;
    const float* Abase = (MODE==1) ? g_h2all : A;
    const int tid = threadIdx.x;
    const int bm = blockIdx.y*64, bn = blockIdx.x*64;
    const int r = tid>>2, q = tid&3;
    const float* arow = (MODE==0) ? Abase + (size_t)gidx[bm+r]*K : Abase + (size_t)(bm+r)*K;
    const int nrow = bn + r;
    const bool bok = nrow < N;
    const float* brow = Bm + (size_t)(bok ? nrow : (N-1))*K;
    const int tx = tid&15, ty = tid>>4;
    ull acc[4][2];
#pragma unroll
    for (int i=0;i<4;++i){ acc[i][0]=0ull; acc[i][1]=0ull; }
    for (int kc=0;kc<K;kc+=16){
        float4 av = *(const float4*)(arow + kc + q*4);
        float4 bv = *(const float4*)(brow + kc + q*4);
        if (!bok){ bv.x=bv.y=bv.z=bv.w=0.f; }
        __syncthreads();
        As[q*4+0][r]=av.x; As[q*4+1][r]=av.y; As[q*4+2][r]=av.z; As[q*4+3][r]=av.w;
        Bs[q*4+0][r]=bv.x; Bs[q*4+1][r]=bv.y; Bs[q*4+2][r]=bv.z; Bs[q*4+3][r]=bv.w;
        __syncthreads();
#pragma unroll
        for (int k=0;k<16;++k){
            ull b0 = *(const ull*)&Bs[k][tx*4];
            ull b1 = *(const ull*)&Bs[k][tx*4+2];
            float4 a4 = *(const float4*)&As[k][ty*4];
            ull a;
            a=dup2(a4.x); fma2(acc[0][0],a,b0); fma2(acc[0][1],a,b1);
            a=dup2(a4.y); fma2(acc[1][0],a,b0); fma2(acc[1][1],a,b1);
            a=dup2(a4.z); fma2(acc[2][0],a,b0); fma2(acc[2][1],a,b1);
            a=dup2(a4.w); fma2(acc[3][0],a,b0); fma2(acc[3][1],a,b1);
        }
    }
#pragma unroll
    for (int i=0;i<4;++i){
        int row = bm + ty*4 + i;
        float2 c0=unp2(acc[i][0]), c1=unp2(acc[i][1]);
        float v[4]={c0.x,c0.y,c1.x,c1.y};
#pragma unroll
        for (int j=0;j<4;++j){
            int col = bn + tx*4 + j;
            if (col < N) C[(size_t)row*N + col] = v[j] + bias[col];
        }
    }
}

// =======================================================================
// A-pack prep: fp32 W -> gate-interleaved, SW128-preswizzled bf16 hi/lo
// =======================================================================
template<int L>
__global__ void prep_A(const float* __restrict__ Wi, const float* __restrict__ Wh)
{
    using C = LC<L>;
    size_t idx = (size_t)blockIdx.x*256 + threadIdx.x;
    size_t total = (size_t)C::NJB*C::NCH*8192;
    if (idx >= total) return;
    int kk  = (int)(idx & 63);
    int row = (int)((idx>>6) & 127);
    int ch  = (int)((idx>>13) % C::NCH);
    int jb  = (int)(idx / ((size_t)C::NCH*8192));
    int gate = row>>5, j = jb*32 + (row&31);
    int kabs = ch*64 + kk;
    float v = 0.f;
    if (j < C::OUT){
        if (kabs < C::KX)                 v = Wi[(size_t)(gate*C::OUT + j)*C::KX + kabs];
        else if (kabs < C::KX + C::KH)    v = Wh[(size_t)(gate*C::OUT + j)*C::KH + (kabs - C::KX)];
    }
    __nv_bfloat16 h = __float2bfloat16(v);
    __nv_bfloat16 l = __float2bfloat16(v - __bfloat162float(h));
    uint32_t pos = SWZ((uint32_t)(row*128 + kk*2)) >> 1;
    __nv_bfloat16* Ap = Apack<L>() + (size_t)(jb*C::NCH + ch)*16384;
    Ap[pos] = h;
    Ap[8192 + pos] = l;
}

// =======================================================================
// Fused layer step: MMA (m16n8k16 bf16, 3 split passes) + last-CTA-reduces
// pointwise. grid = NJB*S CTAs, 128 threads = 4 warps. Node count per step
// drops from 6 to 3 (keeps the graph-exec param pool inside its first
// chunk, which the R10 run showed is load-bearing for the harness rule).
// =======================================================================
#define STGB 40960
#define SMEM_MMA (4*STGB)

template<int L>
__global__ __launch_bounds__(128) void layer_step(
    const float* __restrict__ bx, const float* __restrict__ bhh, int t)
{
    using C = LC<L>;
    extern __shared__ __align__(128) char sm[];
    __shared__ int s_last;
    const int tid = threadIdx.x;
    const int w = tid >> 5, ln = tid & 31;
    const int jb = blockIdx.x / C::S, s = blockIdx.x % C::S;
    const int c0 = (s*C::NCH)/C::S, c1n = ((s+1)*C::NCH)/C::S, n = c1n - c0;
    const int par = t & 1;
    uint32_t sb = smem_u32(sm);
    const __nv_bfloat16* Ab = Apack<L>() + (size_t)(jb*C::NCH + c0)*16384;
    const __nv_bfloat16* Bb = Bpack<L>(par) + (size_t)c0*4096;

    auto fill = [&](int i){
        uint32_t dst = sb + (i & 3)*STGB;
        const char* a = (const char*)(Ab + (size_t)i*16384);
#pragma unroll
        for (int r=0;r<16;r++) cpa16(dst + r*2048 + tid*16, a + r*2048 + tid*16);
        const char* b = (const char*)(Bb + (size_t)i*4096);
#pragma unroll
        for (int r=0;r<4;r++) cpa16(dst + 32768 + r*2048 + tid*16, b + r*2048 + tid*16);
    };
    for (int i=0;i<4;i++){ if (i<n) fill(i); CPA_COMMIT(); }

    float acc[2][4][4];
#pragma unroll
    for (int mi=0;mi<2;mi++)
#pragma unroll
        for (int ni=0;ni<4;ni++)
#pragma unroll
            for (int q=0;q<4;q++) acc[mi][ni][q]=0.f;

    const int arow = w*32 + (ln&7) + ((ln>>3)&1)*8;   // + mi*16
    const int akad = ((ln>>4)&1)*16;
    const int brow = ((ln>>4)&1)*8 + (ln&7);
    const int bkad = ((ln>>3)&1)*16;

    for (int i=0;i<n;i++){
        asm volatile("cp.async.wait_group 3;" ::: "memory");
        __syncthreads();
        uint32_t so = sb + (i & 3)*STGB;
#pragma unroll
        for (int p=0;p<3;p++){
            uint32_t aoff = so + ((p==2)?16384u:0u);
            uint32_t boff = so + ((p==1)?36864u:32768u);
#pragma unroll
            for (int ks=0;ks<4;ks++){
                const int kb = ks*32;
                uint32_t bf[8];
                uint32_t ba0 = boff + SWZ((uint32_t)(brow*128 + kb + bkad));
                uint32_t ba1 = boff + SWZ((uint32_t)((brow+16)*128 + kb + bkad));
                asm volatile("ldmatrix.sync.aligned.m8n8.x4.shared.b16 {%0,%1,%2,%3}, [%4];"
                    : "=r"(bf[0]),"=r"(bf[1]),"=r"(bf[2]),"=r"(bf[3]) : "r"(ba0));
                asm volatile("ldmatrix.sync.aligned.m8n8.x4.shared.b16 {%0,%1,%2,%3}, [%4];"
                    : "=r"(bf[4]),"=r"(bf[5]),"=r"(bf[6]),"=r"(bf[7]) : "r"(ba1));
#pragma unroll
                for (int mi=0;mi<2;mi++){
                    uint32_t af[4];
                    uint32_t aa = aoff + SWZ((uint32_t)((arow+mi*16)*128 + kb + akad));
                    asm volatile("ldmatrix.sync.aligned.m8n8.x4.shared.b16 {%0,%1,%2,%3}, [%4];"
                        : "=r"(af[0]),"=r"(af[1]),"=r"(af[2]),"=r"(af[3]) : "r"(aa));
#pragma unroll
                    for (int ni=0;ni<4;ni++){
                        asm volatile(
                            "mma.sync.aligned.m16n8k16.row.col.f32.bf16.bf16.f32 "
                            "{%0,%1,%2,%3}, {%4,%5,%6,%7}, {%8,%9}, {%0,%1,%2,%3};"
                            : "+f"(acc[mi][ni][0]),"+f"(acc[mi][ni][1]),
                              "+f"(acc[mi][ni][2]),"+f"(acc[mi][ni][3])
                            : "r"(af[0]),"r"(af[1]),"r"(af[2]),"r"(af[3]),
                              "r"(bf[ni*2]),"r"(bf[ni*2+1]));
                    }
                }
            }
        }
        __syncthreads();
        if (i+4 < n) fill(i+4);
        CPA_COMMIT();
    }

    // write partials: P[row*32 + batch]
    float* P = Ppart<L>() + (size_t)blockIdx.x*4096;
#pragma unroll
    for (int mi=0;mi<2;mi++){
        int row = w*32 + mi*16 + (ln>>2);
#pragma unroll
        for (int ni=0;ni<4;ni++){
            int col = ni*8 + (ln&3)*2;
            *(float2*)(P + row*32 + col)     = make_float2(acc[mi][ni][0], acc[mi][ni][1]);
            *(float2*)(P + (row+8)*32 + col) = make_float2(acc[mi][ni][2], acc[mi][ni][3]);
        }
    }

    // ---- last-CTA-for-this-jb does the fused pointwise ----
    __threadfence();
    __syncthreads();
    if (tid == 0){
        int old = atomicAdd(&g_cnt[L][jb], 1);
        s_last = (old == C::S - 1);
        if (s_last) g_cnt[L][jb] = 0;     // reset for the next launch
    }
    __syncthreads();
    if (!s_last) return;
    __threadfence();                       // acquire producers' partials

    const float* Pb = Ppart<L>() + (size_t)jb*C::S*4096;
    float* cst = g_c[L];
#pragma unroll
    for (int it=0; it<8; ++it){
        int item = tid + it*128;
        int jj = item>>5, b = item&31;
        int j = jb*32 + jj;
        if (j >= C::OUT) continue;
        float pre[4];
#pragma unroll
        for (int g=0; g<4; ++g){
            float sum = 0.f;
            for (int s2=0; s2<C::S; ++s2)
                sum += Pb[(size_t)s2*4096 + (g*32+jj)*32 + b];
            pre[g] = sum;
        }
        float ip, fp, op, gp;
        if (L == 0){
            const float* p0 = g_P0 + (size_t)(t*32 + b)*M4H + j;
            ip = pre[0]+p0[0]     +bhh[j];
            fp = pre[1]+p0[HH]    +bhh[HH+j];
            op = pre[2]+p0[2*HH]  +bhh[2*HH+j];
            gp = pre[3]+p0[3*HH]  +bhh[3*HH+j];
        } else {
            ip = pre[0]+bx[j]          +bhh[j];
            fp = pre[1]+bx[C::OUT+j]   +bhh[C::OUT+j];
            op = pre[2]+bx[2*C::OUT+j] +bhh[2*C::OUT+j];
            gp = pre[3]+bx[3*C::OUT+j] +bhh[3*C::OUT+j];
        }
        float gi=1.f/(1.f+expf(-ip)), gf=1.f/(1.f+expf(-fp));
        float go=1.f/(1.f+expf(-op)), gg=tanhf(gp);
        float cn = gf*cst[j*32+b] + gi*gg;
        cst[j*32+b] = cn;
        float hv = go*tanhf(cn);
        g_hf[L][j*32+b] = hv;
        if (L == 0){
            stageB(gB0[par^1], j, b, hv);
            stageB(gB1[par],   j, b, hv);
        } else if (L == 1){
            stageB(gB1[par^1], 1150 + j, b, hv);
            stageB(gB2[par],   j, b, hv);
        } else {
            stageB(gB2[par^1], 1150 + j, b, hv);
            g_h2all[(size_t)(t*32 + b)*EE + j] = hv;
        }
    }
}

// ---- init: c states + seed B packs (parity 0) ----
__global__ void init_states(const float* __restrict__ h0,
                            const float* __restrict__ c0,
                            const float* __restrict__ h0l,
                            const float* __restrict__ c0l)
{
    int idx = blockIdx.x*blockDim.x + threadIdx.x;
    if (idx < HH*BB){
        int k = idx>>5, b = idx&31;
        g_c[0][idx] = c0[b*HH + k];
        g_c[1][idx] = c0[BB*HH + b*HH + k];
        stageB(gB0[0], k,        b, h0[b*HH + k]);
        stageB(gB1[0], 1150 + k, b, h0[BB*HH + b*HH + k]);
    }
    if (idx < EE*BB){
        int k = idx>>5, b = idx&31;
        g_c[2][idx] = c0l[b*EE + k];
        stageB(gB2[0], 1150 + k, b, h0l[b*EE + k]);
    }
}

__global__ void finalize_states(float* __restrict__ out)
{
    const size_t D1 = (size_t)TT*BB*VV;
    const size_t D2 = D1 + 2*BB*HH;
    const size_t D3 = D2 + BB*EE;
    const size_t D4 = D3 + 2*BB*HH;
    int idx = blockIdx.x*blockDim.x + threadIdx.x;
    if (idx < HH*BB){
        int k = idx>>5, b = idx&31;
        out[D1 + b*HH + k]           = g_hf[0][idx];
        out[D1 + BB*HH + b*HH + k]   = g_hf[1][idx];
        out[D3 + b*HH + k]           = g_c[0][idx];
        out[D3 + BB*HH + b*HH + k]   = g_c[1][idx];
    }
    if (idx < EE*BB){
        int k = idx>>5, b = idx&31;
        out[D2 + b*EE + k] = g_hf[2][idx];
        out[D4 + b*EE + k] = g_c[2][idx];
    }
}

// =======================================================================
extern "C" void kernel_launch(void* const* d_in, const int* in_sizes, int n_in,
                              void* d_out, int out_size)
{
    const int*   x    = (const int*)  d_in[0];
    const float* h0   = (const float*)d_in[1];
    const float* c0   = (const float*)d_in[2];
    const float* h0l  = (const float*)d_in[3];
    const float* c0l  = (const float*)d_in[4];
    const float* emb  = (const float*)d_in[5];
    const float* Wi0  = (const float*)d_in[6];
    const float* bi0  = (const float*)d_in[7];
    const float* Wh0  = (const float*)d_in[8];
    const float* bh0  = (const float*)d_in[9];
    const float* Wi1  = (const float*)d_in[10];
    const float* bi1  = (const float*)d_in[11];
    const float* Wh1  = (const float*)d_in[12];
    const float* bh1  = (const float*)d_in[13];
    const float* Wi2  = (const float*)d_in[14];
    const float* bi2  = (const float*)d_in[15];
    const float* Wh2  = (const float*)d_in[16];
    const float* bh2  = (const float*)d_in[17];
    const float* decW = (const float*)d_in[18];
    const float* decb = (const float*)d_in[19];
    float* out = (float*)d_out;

    cudaFuncSetAttribute(layer_step<0>, cudaFuncAttributeMaxDynamicSharedMemorySize, SMEM_MMA);
    cudaFuncSetAttribute(layer_step<1>, cudaFuncAttributeMaxDynamicSharedMemorySize, SMEM_MMA);
    cudaFuncSetAttribute(layer_step<2>, cudaFuncAttributeMaxDynamicSharedMemorySize, SMEM_MMA);

    init_states<<<(HH*BB + 255)/256, 256>>>(h0, c0, h0l, c0l);

    prep_A<0><<<(36*18*8192 + 255)/256, 256>>>(nullptr, Wh0);
    prep_A<1><<<(36*36*8192 + 255)/256, 256>>>(Wi1, Wh1);
    prep_A<2><<<(13*25*8192 + 255)/256, 256>>>(Wi2, Wh2);

    {   // P0 = emb[x] @ Wi0^T + bi0
        dim3 g((M4H + 63)/64, NROW/64);
        sgemm_nt<0><<<g, 256>>>(emb, x, Wi0, bi0, nullptr, M4H);
    }

    for (int t = 0; t < TT; ++t){
        layer_step<0><<<36*4, 128, SMEM_MMA>>>(bh0, bh0, t);
        layer_step<1><<<36*4, 128, SMEM_MMA>>>(bi1, bh1, t);
        layer_step<2><<<13*8, 128, SMEM_MMA>>>(bi2, bh2, t);
    }

    {   // decoder
        dim3 g((VV + 63)/64, NROW/64);
        sgemm_nt<1><<<g, 256>>>(nullptr, nullptr, decW, decb, out, VV);
    }

    finalize_states<<<(HH*BB + 255)/256, 256>>>(out);
}